// round 3
// baseline (speedup 1.0000x reference)
#include <cuda_runtime.h>
#include <math.h>

#define B 256
#define L 200
#define D 512
#define K3 1536
#define NB 128
#define THR 256

// ---------------- device scratch ----------------
__device__ float g_xproj[(size_t)B * L * K3];
__device__ float g_sstate[(size_t)B * L * D];
__device__ float g_apre0[(size_t)B * L * D];
__device__ float g_apre1[(size_t)B * L * D];
__device__ float g_apre2[(size_t)B * L * D];
__device__ float g_uvec[B * D];
__device__ float g_att[B * L];
__device__ float g_hA[B * D];
__device__ float g_hB[B * D];
__device__ float g_rh[B * D];

__device__ unsigned g_barcount = 0;
__device__ volatile unsigned g_barphase = 0;

__device__ __forceinline__ float sigmoidf_(float x) { return 1.f / (1.f + expf(-x)); }

__device__ __forceinline__ void grid_barrier(int nb)
{
    __syncthreads();
    if (threadIdx.x == 0) {
        __threadfence();
        unsigned ph = g_barphase;
        if (atomicAdd(&g_barcount, 1u) == (unsigned)nb - 1u) {
            g_barcount = 0;
            __threadfence();
            g_barphase = ph + 1u;
        } else {
            while (g_barphase == ph) { __nanosleep(32); }
        }
    }
    __syncthreads();
}

// ---------------- fp32 GEMM: C[M,N] = A[M,512] * W[N,512]^T (+bias) ----------------
// 128x128 tile, BK=16, 256 threads, 8x8 micro.
// a_sel: 0=Aparam, 1=g_sstate. c_sel: 0=g_xproj 1=g_uvec 2=g_apre0 3=g_apre1 4=g_apre2
__global__ void gemm_tile128(const float* __restrict__ Aparam, int a_sel,
                             const float* __restrict__ W, int ldw,
                             const float* __restrict__ bias,
                             int c_sel, int Ntot)
{
    const int K = 512;
    const float* A = (a_sel == 0) ? Aparam : g_sstate;
    float* C = (c_sel == 0) ? g_xproj : (c_sel == 1) ? g_uvec :
               (c_sel == 2) ? g_apre0 : (c_sel == 3) ? g_apre1 : g_apre2;

    __shared__ float As[16][132];
    __shared__ float Ws[16][132];

    const int m0 = blockIdx.y * 128;
    const int n0 = blockIdx.x * 128;
    const int tid = threadIdx.x;
    const int tx = tid & 15, ty = tid >> 4;
    const int lr = tid >> 1;
    const int lc = (tid & 1) * 4;

    float acc[8][8];
#pragma unroll
    for (int i = 0; i < 8; i++)
#pragma unroll
        for (int j = 0; j < 8; j++) acc[i][j] = 0.f;

    const float* Abase = A + (size_t)(m0 + lr) * K + lc;
    const float* Wbase = W + (size_t)(n0 + lr) * ldw + lc;

    for (int k0 = 0; k0 < K; k0 += 16) {
        float4 a0 = *(const float4*)(Abase + k0);
        float4 a1 = *(const float4*)(Abase + k0 + 8);
        float4 w0 = *(const float4*)(Wbase + k0);
        float4 w1 = *(const float4*)(Wbase + k0 + 8);
        __syncthreads();
        As[lc + 0][lr] = a0.x; As[lc + 1][lr] = a0.y; As[lc + 2][lr] = a0.z; As[lc + 3][lr] = a0.w;
        As[lc + 8][lr] = a1.x; As[lc + 9][lr] = a1.y; As[lc +10][lr] = a1.z; As[lc +11][lr] = a1.w;
        Ws[lc + 0][lr] = w0.x; Ws[lc + 1][lr] = w0.y; Ws[lc + 2][lr] = w0.z; Ws[lc + 3][lr] = w0.w;
        Ws[lc + 8][lr] = w1.x; Ws[lc + 9][lr] = w1.y; Ws[lc +10][lr] = w1.z; Ws[lc +11][lr] = w1.w;
        __syncthreads();
#pragma unroll
        for (int kk = 0; kk < 16; kk++) {
            float av[8], wv[8];
            *(float4*)&av[0] = *(const float4*)&As[kk][ty * 8];
            *(float4*)&av[4] = *(const float4*)&As[kk][ty * 8 + 4];
            *(float4*)&wv[0] = *(const float4*)&Ws[kk][tx * 8];
            *(float4*)&wv[4] = *(const float4*)&Ws[kk][tx * 8 + 4];
#pragma unroll
            for (int i = 0; i < 8; i++)
#pragma unroll
                for (int j = 0; j < 8; j++)
                    acc[i][j] += av[i] * wv[j];
        }
    }

#pragma unroll
    for (int i = 0; i < 8; i++) {
        int m = m0 + ty * 8 + i;
#pragma unroll
        for (int j = 0; j < 8; j++) {
            int n = n0 + tx * 8 + j;
            C[(size_t)m * Ntot + n] = acc[i][j] + (bias ? bias[n] : 0.f);
        }
    }
}

// ---------------- GRU persistent kernel ----------------
// 128 CTAs = 4 m-tiles(64) x 32 d-tiles(16); 256 threads; weights resident in smem.
__global__ void gru_kernel(const float* __restrict__ whh, const float* __restrict__ bhh)
{
    extern __shared__ float ws[];            // [512][48]  (k, gate*16+d)
    __shared__ float hs[32][68];

    const int nb = gridDim.x;
    const int bid = blockIdx.x;
    const int m0 = (bid >> 5) * 64;
    const int d0 = (bid & 31) * 16;
    const int tid = threadIdx.x;
    const int mt = tid >> 4;                 // 0..15 -> 4 m each
    const int dt = tid & 15;                 // d within tile
    const int m_l = tid >> 2;                // 0..63 (stage rows)
    const int kq = (tid & 3) * 8;            // stage k offset

    // load recurrent weight slice once: ws[k][g*16+d] = whh[(g*512+d0+d)*512 + k]
    for (int idx = tid; idx < 3 * 512 * 16; idx += THR) {
        int g = idx >> 13;
        int rem = idx & 8191;
        int k = rem >> 4;
        int d = rem & 15;
        ws[k * 48 + g * 16 + d] = __ldg(whh + (size_t)(g * 512 + d0 + d) * D + k);
    }

    // zero h0
    for (int i = tid; i < 1024; i += THR)
        g_hA[bid * 1024 + i] = 0.f;

    const int d = d0 + dt;
    const float bR = bhh[d], bZ = bhh[512 + d], bN = bhh[1024 + d];

    grid_barrier(nb);

    for (int l = 0; l < L; l++) {
        const float* __restrict__ hin = (l & 1) ? g_hB : g_hA;
        float* __restrict__ hout = (l & 1) ? g_hA : g_hB;

        float accR[4] = {}, accZ[4] = {}, accN[4] = {};

        for (int k0 = 0; k0 < D; k0 += 32) {
            const float4* p = (const float4*)(hin + (size_t)(m0 + m_l) * D + k0 + kq);
            float4 v0 = __ldcg(p);
            float4 v1 = __ldcg(p + 1);
            __syncthreads();
            hs[kq + 0][m_l] = v0.x; hs[kq + 1][m_l] = v0.y; hs[kq + 2][m_l] = v0.z; hs[kq + 3][m_l] = v0.w;
            hs[kq + 4][m_l] = v1.x; hs[kq + 5][m_l] = v1.y; hs[kq + 6][m_l] = v1.z; hs[kq + 7][m_l] = v1.w;
            __syncthreads();
#pragma unroll
            for (int kk = 0; kk < 32; kk++) {
                float4 hv = *(const float4*)&hs[kk][mt * 4];
                const float* wrow = ws + (k0 + kk) * 48;
                float wr = wrow[dt], wz = wrow[16 + dt], wn = wrow[32 + dt];
                float hvv[4] = {hv.x, hv.y, hv.z, hv.w};
#pragma unroll
                for (int i = 0; i < 4; i++) {
                    accR[i] += hvv[i] * wr;
                    accZ[i] += hvv[i] * wz;
                    accN[i] += hvv[i] * wn;
                }
            }
        }

#pragma unroll
        for (int i = 0; i < 4; i++) {
            int m = m0 + mt * 4 + i;
            size_t xb = ((size_t)m * L + l) * (size_t)K3 + d;
            float xr = g_xproj[xb], xz = g_xproj[xb + 512], xn = g_xproj[xb + 1024];
            float r = sigmoidf_(xr + accR[i] + bR);
            float z = sigmoidf_(xz + accZ[i] + bZ);
            float n = tanhf(xn + r * (accN[i] + bN));
            float hp = __ldcg(hin + (size_t)m * D + d);
            float hnew = (1.f - z) * n + z * hp;
            hout[(size_t)m * D + d] = hnew;
            g_sstate[((size_t)m * L + l) * (size_t)D + d] = hnew;
        }
        grid_barrier(nb);
    }
}

// ---------------- attention: logits + softmax over L ----------------
__global__ void attn_kernel()
{
    int b = blockIdx.x, tid = threadIdx.x;
    __shared__ float us[D];
    __shared__ float logits[L];
    __shared__ float red[8];
    for (int i = tid; i < D; i += 256) us[i] = g_uvec[b * D + i];
    __syncthreads();
    int wid = tid >> 5, lane = tid & 31;
    for (int l = wid; l < L; l += 8) {
        const float* sp = g_sstate + ((size_t)b * L + l) * D;
        float s = 0.f;
#pragma unroll
        for (int q = 0; q < 16; q++) s += sp[lane + 32 * q] * us[lane + 32 * q];
#pragma unroll
        for (int o = 16; o > 0; o >>= 1) s += __shfl_down_sync(0xffffffffu, s, o);
        if (lane == 0) logits[l] = s;
    }
    __syncthreads();
    float m = -1e30f;
    for (int i = tid; i < L; i += 256) m = fmaxf(m, logits[i]);
#pragma unroll
    for (int o = 16; o > 0; o >>= 1) m = fmaxf(m, __shfl_xor_sync(0xffffffffu, m, o));
    if (lane == 0) red[wid] = m;
    __syncthreads();
    m = red[0];
#pragma unroll
    for (int i = 1; i < 8; i++) m = fmaxf(m, red[i]);
    __syncthreads();
    float s = 0.f;
    for (int i = tid; i < L; i += 256) { float e = expf(logits[i] - m); logits[i] = e; s += e; }
#pragma unroll
    for (int o = 16; o > 0; o >>= 1) s += __shfl_xor_sync(0xffffffffu, s, o);
    if (lane == 0) red[wid] = s;
    __syncthreads();
    s = 0.f;
#pragma unroll
    for (int i = 0; i < 8; i++) s += red[i];
    float inv = 1.f / s;
    for (int i = tid; i < L; i += 256) g_att[b * L + i] = logits[i] * inv;
}

// ---------------- AUGRU persistent kernel ----------------
// Same tiling as GRU. Weight slice in smem: g0=reset_h, g1=update_h, g2=hhat_h.
__global__ void augru_kernel(const float* __restrict__ reset_w,
                             const float* __restrict__ update_w,
                             const float* __restrict__ hhat_w)
{
    extern __shared__ float ws[];            // [512][48]
    __shared__ float hs[32][68];

    const int nb = gridDim.x;
    const int bid = blockIdx.x;
    const int m0 = (bid >> 5) * 64;
    const int d0 = (bid & 31) * 16;
    const int tid = threadIdx.x;
    const int mt = tid >> 4;
    const int dt = tid & 15;
    const int m_l = tid >> 2;
    const int kq = (tid & 3) * 8;
    const int d = d0 + dt;

    for (int idx = tid; idx < 3 * 512 * 16; idx += THR) {
        int g = idx >> 13;
        int rem = idx & 8191;
        int k = rem >> 4;
        int dd = rem & 15;
        const float* src = (g == 0) ? reset_w : (g == 1) ? update_w : hhat_w;
        // h-part = columns [0, D) of the [D, 2D] matrices
        ws[k * 48 + g * 16 + dd] = __ldg(src + (size_t)(d0 + dd) * (2 * D) + k);
    }

    // init h from GRU final state (g_hA), keep elementwise copy in registers
    float hval[4], uu[4];
#pragma unroll
    for (int i = 0; i < 4; i++) {
        int m = m0 + mt * 4 + i;
        hval[i] = __ldcg(g_hA + (size_t)m * D + d);
        g_hB[(size_t)m * D + d] = hval[i];
    }
    grid_barrier(nb);

    for (int l = 0; l < L; l++) {
        // ---- phase 1: r, u gates (GEMM over h) ----
        float accR[4] = {}, accU[4] = {};
        for (int k0 = 0; k0 < D; k0 += 32) {
            const float4* p = (const float4*)(g_hB + (size_t)(m0 + m_l) * D + k0 + kq);
            float4 v0 = __ldcg(p);
            float4 v1 = __ldcg(p + 1);
            __syncthreads();
            hs[kq + 0][m_l] = v0.x; hs[kq + 1][m_l] = v0.y; hs[kq + 2][m_l] = v0.z; hs[kq + 3][m_l] = v0.w;
            hs[kq + 4][m_l] = v1.x; hs[kq + 5][m_l] = v1.y; hs[kq + 6][m_l] = v1.z; hs[kq + 7][m_l] = v1.w;
            __syncthreads();
#pragma unroll
            for (int kk = 0; kk < 32; kk++) {
                float4 hv = *(const float4*)&hs[kk][mt * 4];
                const float* wrow = ws + (k0 + kk) * 48;
                float wr = wrow[dt], wu = wrow[16 + dt];
                float hvv[4] = {hv.x, hv.y, hv.z, hv.w};
#pragma unroll
                for (int i = 0; i < 4; i++) {
                    accR[i] += hvv[i] * wr;
                    accU[i] += hvv[i] * wu;
                }
            }
        }
#pragma unroll
        for (int i = 0; i < 4; i++) {
            int m = m0 + mt * 4 + i;
            size_t ap = ((size_t)m * L + l) * (size_t)D + d;
            float r = sigmoidf_(g_apre0[ap] + accR[i]);
            float u = sigmoidf_(g_apre1[ap] + accU[i]);
            uu[i] = g_att[m * L + l] * u;
            g_rh[(size_t)m * D + d] = r * hval[i];
        }
        grid_barrier(nb);

        // ---- phase 2: h_hat (GEMM over r*h), update h ----
        float accH[4] = {};
        for (int k0 = 0; k0 < D; k0 += 32) {
            const float4* p = (const float4*)(g_rh + (size_t)(m0 + m_l) * D + k0 + kq);
            float4 v0 = __ldcg(p);
            float4 v1 = __ldcg(p + 1);
            __syncthreads();
            hs[kq + 0][m_l] = v0.x; hs[kq + 1][m_l] = v0.y; hs[kq + 2][m_l] = v0.z; hs[kq + 3][m_l] = v0.w;
            hs[kq + 4][m_l] = v1.x; hs[kq + 5][m_l] = v1.y; hs[kq + 6][m_l] = v1.z; hs[kq + 7][m_l] = v1.w;
            __syncthreads();
#pragma unroll
            for (int kk = 0; kk < 32; kk++) {
                float4 hv = *(const float4*)&hs[kk][mt * 4];
                float wh = ws[(k0 + kk) * 48 + 32 + dt];
                accH[0] += hv.x * wh;
                accH[1] += hv.y * wh;
                accH[2] += hv.z * wh;
                accH[3] += hv.w * wh;
            }
        }
#pragma unroll
        for (int i = 0; i < 4; i++) {
            int m = m0 + mt * 4 + i;
            size_t ap = ((size_t)m * L + l) * (size_t)D + d;
            float hh = tanhf(g_apre2[ap] + accH[i]);
            hval[i] = (1.f - uu[i]) * hval[i] + uu[i] * hh;
            g_hB[(size_t)m * D + d] = hval[i];
        }
        grid_barrier(nb);
    }
}

__global__ void copy_out_kernel(float* __restrict__ out)
{
    int i = blockIdx.x * 512 + threadIdx.x;
    out[i] = g_hB[i];
}

// ---------------- launch ----------------
extern "C" void kernel_launch(void* const* d_in, const int* in_sizes, int n_in,
                              void* d_out, int out_size)
{
    const float* session  = (const float*)d_in[0];
    const float* target   = (const float*)d_in[1];
    const float* w        = (const float*)d_in[2];
    const float* gru_wih  = (const float*)d_in[3];
    const float* gru_whh  = (const float*)d_in[4];
    const float* gru_bih  = (const float*)d_in[5];
    const float* gru_bhh  = (const float*)d_in[6];
    const float* reset_w  = (const float*)d_in[7];
    const float* reset_b  = (const float*)d_in[8];
    const float* update_w = (const float*)d_in[9];
    const float* update_b = (const float*)d_in[10];
    const float* hhat_w   = (const float*)d_in[11];
    const float* hhat_b   = (const float*)d_in[12];
    float* out = (float*)d_out;

    const int WS_BYTES = 512 * 48 * sizeof(float);   // 98304
    cudaFuncSetAttribute(gru_kernel,   cudaFuncAttributeMaxDynamicSharedMemorySize, WS_BYTES);
    cudaFuncSetAttribute(augru_kernel, cudaFuncAttributeMaxDynamicSharedMemorySize, WS_BYTES);

    // 1) x_proj = session @ wih^T + bih   [51200, 1536]
    gemm_tile128<<<dim3(12, 400), 256>>>(session, 0, gru_wih, 512, gru_bih, 0, K3);
    // 2) u = target @ w^T                 [256, 512]
    gemm_tile128<<<dim3(4, 2), 256>>>(target, 0, w, 512, (const float*)nullptr, 1, D);
    // 3) GRU recurrence
    gru_kernel<<<NB, THR, WS_BYTES>>>(gru_whh, gru_bhh);
    // 4) AUGRU x-side pre-projections: s_state @ W[:, D:2D]^T + b
    gemm_tile128<<<dim3(4, 400), 256>>>(session, 1, reset_w  + D, 2 * D, reset_b,  2, D);
    gemm_tile128<<<dim3(4, 400), 256>>>(session, 1, update_w + D, 2 * D, update_b, 3, D);
    gemm_tile128<<<dim3(4, 400), 256>>>(session, 1, hhat_w   + D, 2 * D, hhat_b,   4, D);
    // 5) attention softmax
    attn_kernel<<<B, 256>>>();
    // 6) AUGRU recurrence
    augru_kernel<<<NB, THR, WS_BYTES>>>(reset_w, update_w, hhat_w);
    // 7) output
    copy_out_kernel<<<B, 512>>>(out);
}

// round 4
// speedup vs baseline: 1.0599x; 1.0599x over previous
#include <cuda_runtime.h>
#include <math.h>

#define B 256
#define L 200
#define D 512
#define K3 1536
#define NB 128
#define THR 256

// ---------------- device scratch ----------------
__device__ float g_xproj[(size_t)B * L * K3];
__device__ float g_sstate[(size_t)B * L * D];
__device__ float g_apre0[(size_t)B * L * D];
__device__ float g_apre1[(size_t)B * L * D];
__device__ float g_apre2[(size_t)B * L * D];
__device__ float g_uvec[B * D];
__device__ float g_att[B * L];
__device__ float g_hA[B * D];
__device__ float g_hB[B * D];
__device__ float g_rh[B * D];

__device__ volatile int g_flagG[NB];
__device__ volatile int g_flagA[NB];

__global__ void reset_flags_kernel()
{
    int i = threadIdx.x;
    if (i < NB) { g_flagG[i] = 0; g_flagA[i] = 0; }
}

__device__ __forceinline__ float sigmoidf_(float x) { return 1.f / (1.f + expf(-x)); }

// wait until all 32 flags of this m-group reach target
__device__ __forceinline__ void group_wait(volatile int* flags, int base, int target)
{
    if (threadIdx.x < 32) {
        while (true) {
            int v = flags[base + threadIdx.x];
            if (!__any_sync(0xffffffffu, v < target)) break;
            __nanosleep(20);
        }
    }
    __syncthreads();
}

__device__ __forceinline__ void group_arrive(volatile int* flags, int bid, int val)
{
    __threadfence();
    __syncthreads();
    if (threadIdx.x == 0) flags[bid] = val;
}

// ---------------- fp32 GEMM: C[M,N] = A[M,512] * W[N,512]^T (+bias) ----------------
// 128x128 tile, BK=16 double-buffered, 256 threads, 8x8 micro.
__global__ void __launch_bounds__(256) gemm_tile128(
        const float* __restrict__ Aparam, int a_sel,
        const float* __restrict__ W, int ldw,
        const float* __restrict__ bias,
        int c_sel, int Ntot)
{
    const int K = 512;
    const float* A = (a_sel == 0) ? Aparam : g_sstate;
    float* C = (c_sel == 0) ? g_xproj : (c_sel == 1) ? g_uvec :
               (c_sel == 2) ? g_apre0 : (c_sel == 3) ? g_apre1 : g_apre2;

    __shared__ float As[2][16][132];
    __shared__ float Ws[2][16][132];

    const int m0 = blockIdx.y * 128;
    const int n0 = blockIdx.x * 128;
    const int tid = threadIdx.x;
    const int tx = tid & 15, ty = tid >> 4;
    const int lr = tid >> 1;
    const int lc = (tid & 1) * 4;

    float acc[8][8];
#pragma unroll
    for (int i = 0; i < 8; i++)
#pragma unroll
        for (int j = 0; j < 8; j++) acc[i][j] = 0.f;

    const float* Abase = A + (size_t)(m0 + lr) * K + lc;
    const float* Wbase = W + (size_t)(n0 + lr) * ldw + lc;

    // prologue: chunk 0
    float4 a0 = *(const float4*)(Abase);
    float4 a1 = *(const float4*)(Abase + 8);
    float4 w0 = *(const float4*)(Wbase);
    float4 w1 = *(const float4*)(Wbase + 8);
    As[0][lc + 0][lr] = a0.x; As[0][lc + 1][lr] = a0.y; As[0][lc + 2][lr] = a0.z; As[0][lc + 3][lr] = a0.w;
    As[0][lc + 8][lr] = a1.x; As[0][lc + 9][lr] = a1.y; As[0][lc +10][lr] = a1.z; As[0][lc +11][lr] = a1.w;
    Ws[0][lc + 0][lr] = w0.x; Ws[0][lc + 1][lr] = w0.y; Ws[0][lc + 2][lr] = w0.z; Ws[0][lc + 3][lr] = w0.w;
    Ws[0][lc + 8][lr] = w1.x; Ws[0][lc + 9][lr] = w1.y; Ws[0][lc +10][lr] = w1.z; Ws[0][lc +11][lr] = w1.w;
    __syncthreads();

    for (int c = 0; c < 32; c++) {
        if (c < 31) {
            int k0 = (c + 1) * 16;
            a0 = *(const float4*)(Abase + k0);
            a1 = *(const float4*)(Abase + k0 + 8);
            w0 = *(const float4*)(Wbase + k0);
            w1 = *(const float4*)(Wbase + k0 + 8);
        }
        const int buf = c & 1;
#pragma unroll
        for (int kk = 0; kk < 16; kk++) {
            float av[8], wv[8];
            *(float4*)&av[0] = *(const float4*)&As[buf][kk][ty * 8];
            *(float4*)&av[4] = *(const float4*)&As[buf][kk][ty * 8 + 4];
            *(float4*)&wv[0] = *(const float4*)&Ws[buf][kk][tx * 8];
            *(float4*)&wv[4] = *(const float4*)&Ws[buf][kk][tx * 8 + 4];
#pragma unroll
            for (int i = 0; i < 8; i++)
#pragma unroll
                for (int j = 0; j < 8; j++)
                    acc[i][j] += av[i] * wv[j];
        }
        __syncthreads();
        if (c < 31) {
            const int nbuf = buf ^ 1;
            As[nbuf][lc + 0][lr] = a0.x; As[nbuf][lc + 1][lr] = a0.y; As[nbuf][lc + 2][lr] = a0.z; As[nbuf][lc + 3][lr] = a0.w;
            As[nbuf][lc + 8][lr] = a1.x; As[nbuf][lc + 9][lr] = a1.y; As[nbuf][lc +10][lr] = a1.z; As[nbuf][lc +11][lr] = a1.w;
            Ws[nbuf][lc + 0][lr] = w0.x; Ws[nbuf][lc + 1][lr] = w0.y; Ws[nbuf][lc + 2][lr] = w0.z; Ws[nbuf][lc + 3][lr] = w0.w;
            Ws[nbuf][lc + 8][lr] = w1.x; Ws[nbuf][lc + 9][lr] = w1.y; Ws[nbuf][lc +10][lr] = w1.z; Ws[nbuf][lc +11][lr] = w1.w;
            __syncthreads();
        }
    }

#pragma unroll
    for (int i = 0; i < 8; i++) {
        int m = m0 + ty * 8 + i;
#pragma unroll
        for (int j = 0; j < 8; j++) {
            int n = n0 + tx * 8 + j;
            C[(size_t)m * Ntot + n] = acc[i][j] + (bias ? bias[n] : 0.f);
        }
    }
}

// ---------------- GRU persistent kernel ----------------
// 128 CTAs = 4 m-groups(64 rows) x 32 d-tiles(16); 256 threads; weights resident in smem.
// Sync: per-m-group flags only (groups are independent chains).
__global__ void __launch_bounds__(THR) gru_kernel(const float* __restrict__ whh,
                                                  const float* __restrict__ bhh)
{
    extern __shared__ float ws[];            // [512][48]  (k, gate*16+d)
    __shared__ float hs[2][32][68];

    const int bid = blockIdx.x;
    const int mb = bid >> 5;
    const int m0 = mb * 64;
    const int fbase = mb * 32;
    const int d0 = (bid & 31) * 16;
    const int tid = threadIdx.x;
    const int mt = tid >> 4;                 // 0..15 -> 4 m each
    const int dt = tid & 15;
    const int m_l = tid >> 2;                // 0..63 (stage rows)
    const int kq = (tid & 3) * 8;            // stage k offset

    for (int idx = tid; idx < 3 * 512 * 16; idx += THR) {
        int g = idx >> 13;
        int rem = idx & 8191;
        int k = rem >> 4;
        int dd = rem & 15;
        ws[k * 48 + g * 16 + dd] = __ldg(whh + (size_t)(g * 512 + d0 + dd) * D + k);
    }
    for (int i = tid; i < 1024; i += THR)    // rows [2*bid, 2*bid+2) -> within group
        g_hA[bid * 1024 + i] = 0.f;

    const int d = d0 + dt;
    const float bR = bhh[d], bZ = bhh[512 + d], bN = bhh[1024 + d];

    group_arrive(g_flagG, bid, 1);           // h^0 ready

    for (int l = 0; l < L; l++) {
        const float* __restrict__ hin = (l & 1) ? g_hB : g_hA;
        float* __restrict__ hout = (l & 1) ? g_hA : g_hB;
        group_wait(g_flagG, fbase, l + 1);

        // prefetch x-side gates + own h_prev (overlaps the GEMM below)
        float xr[4], xz[4], xn[4], hp[4];
#pragma unroll
        for (int i = 0; i < 4; i++) {
            int m = m0 + mt * 4 + i;
            size_t xb = ((size_t)m * L + l) * (size_t)K3 + d;
            xr[i] = __ldcg(&g_xproj[xb]);
            xz[i] = __ldcg(&g_xproj[xb + 512]);
            xn[i] = __ldcg(&g_xproj[xb + 1024]);
            hp[i] = __ldcg(hin + (size_t)m * D + d);
        }

        float accR[4] = {}, accZ[4] = {}, accN[4] = {};

        const float* rowp = hin + (size_t)(m0 + m_l) * D + kq;
        float4 v0 = __ldcg((const float4*)rowp);
        float4 v1 = __ldcg((const float4*)rowp + 1);
        hs[0][kq + 0][m_l] = v0.x; hs[0][kq + 1][m_l] = v0.y; hs[0][kq + 2][m_l] = v0.z; hs[0][kq + 3][m_l] = v0.w;
        hs[0][kq + 4][m_l] = v1.x; hs[0][kq + 5][m_l] = v1.y; hs[0][kq + 6][m_l] = v1.z; hs[0][kq + 7][m_l] = v1.w;
        __syncthreads();

        for (int c = 0; c < 16; c++) {
            if (c < 15) {
                const float* p = rowp + (c + 1) * 32;
                v0 = __ldcg((const float4*)p);
                v1 = __ldcg((const float4*)p + 1);
            }
            const int buf = c & 1;
#pragma unroll
            for (int kk = 0; kk < 32; kk++) {
                float4 hv = *(const float4*)&hs[buf][kk][mt * 4];
                const float* wrow = ws + (size_t)((c << 5) + kk) * 48;
                float wr = wrow[dt], wz = wrow[16 + dt], wn = wrow[32 + dt];
                accR[0] += hv.x * wr; accR[1] += hv.y * wr; accR[2] += hv.z * wr; accR[3] += hv.w * wr;
                accZ[0] += hv.x * wz; accZ[1] += hv.y * wz; accZ[2] += hv.z * wz; accZ[3] += hv.w * wz;
                accN[0] += hv.x * wn; accN[1] += hv.y * wn; accN[2] += hv.z * wn; accN[3] += hv.w * wn;
            }
            __syncthreads();
            if (c < 15) {
                const int nbuf = buf ^ 1;
                hs[nbuf][kq + 0][m_l] = v0.x; hs[nbuf][kq + 1][m_l] = v0.y; hs[nbuf][kq + 2][m_l] = v0.z; hs[nbuf][kq + 3][m_l] = v0.w;
                hs[nbuf][kq + 4][m_l] = v1.x; hs[nbuf][kq + 5][m_l] = v1.y; hs[nbuf][kq + 6][m_l] = v1.z; hs[nbuf][kq + 7][m_l] = v1.w;
                __syncthreads();
            }
        }

#pragma unroll
        for (int i = 0; i < 4; i++) {
            int m = m0 + mt * 4 + i;
            float r = sigmoidf_(xr[i] + accR[i] + bR);
            float z = sigmoidf_(xz[i] + accZ[i] + bZ);
            float n = tanhf(xn[i] + r * (accN[i] + bN));
            float hnew = (1.f - z) * n + z * hp[i];
            __stcg(hout + (size_t)m * D + d, hnew);
            __stcg(&g_sstate[((size_t)m * L + l) * (size_t)D + d], hnew);
        }
        group_arrive(g_flagG, bid, l + 2);
    }
}

// ---------------- attention: logits + softmax over L ----------------
__global__ void attn_kernel()
{
    int b = blockIdx.x, tid = threadIdx.x;
    __shared__ float us[D];
    __shared__ float logits[L];
    __shared__ float red[8];
    for (int i = tid; i < D; i += 256) us[i] = g_uvec[b * D + i];
    __syncthreads();
    int wid = tid >> 5, lane = tid & 31;
    for (int l = wid; l < L; l += 8) {
        const float* sp = g_sstate + ((size_t)b * L + l) * D;
        float s = 0.f;
#pragma unroll
        for (int q = 0; q < 16; q++) s += sp[lane + 32 * q] * us[lane + 32 * q];
#pragma unroll
        for (int o = 16; o > 0; o >>= 1) s += __shfl_down_sync(0xffffffffu, s, o);
        if (lane == 0) logits[l] = s;
    }
    __syncthreads();
    float m = -1e30f;
    for (int i = tid; i < L; i += 256) m = fmaxf(m, logits[i]);
#pragma unroll
    for (int o = 16; o > 0; o >>= 1) m = fmaxf(m, __shfl_xor_sync(0xffffffffu, m, o));
    if (lane == 0) red[wid] = m;
    __syncthreads();
    m = red[0];
#pragma unroll
    for (int i = 1; i < 8; i++) m = fmaxf(m, red[i]);
    __syncthreads();
    float s = 0.f;
    for (int i = tid; i < L; i += 256) { float e = expf(logits[i] - m); logits[i] = e; s += e; }
#pragma unroll
    for (int o = 16; o > 0; o >>= 1) s += __shfl_xor_sync(0xffffffffu, s, o);
    if (lane == 0) red[wid] = s;
    __syncthreads();
    s = 0.f;
#pragma unroll
    for (int i = 0; i < 8; i++) s += red[i];
    float inv = 1.f / s;
    for (int i = tid; i < L; i += 256) g_att[b * L + i] = logits[i] * inv;
}

// ---------------- AUGRU persistent kernel ----------------
__global__ void __launch_bounds__(THR) augru_kernel(const float* __restrict__ reset_w,
                                                    const float* __restrict__ update_w,
                                                    const float* __restrict__ hhat_w)
{
    extern __shared__ float ws[];            // [512][48]
    __shared__ float hs[2][32][68];

    const int bid = blockIdx.x;
    const int mb = bid >> 5;
    const int m0 = mb * 64;
    const int fbase = mb * 32;
    const int d0 = (bid & 31) * 16;
    const int tid = threadIdx.x;
    const int mt = tid >> 4;
    const int dt = tid & 15;
    const int m_l = tid >> 2;
    const int kq = (tid & 3) * 8;
    const int d = d0 + dt;

    for (int idx = tid; idx < 3 * 512 * 16; idx += THR) {
        int g = idx >> 13;
        int rem = idx & 8191;
        int k = rem >> 4;
        int dd = rem & 15;
        const float* src = (g == 0) ? reset_w : (g == 1) ? update_w : hhat_w;
        ws[k * 48 + g * 16 + dd] = __ldg(src + (size_t)(d0 + dd) * (2 * D) + k);
    }

    float hval[4], uu[4];
#pragma unroll
    for (int i = 0; i < 4; i++) {
        int m = m0 + mt * 4 + i;
        hval[i] = __ldcg(g_hA + (size_t)m * D + d);
        __stcg(&g_hB[(size_t)m * D + d], hval[i]);
    }
    group_arrive(g_flagA, bid, 1);

    for (int l = 0; l < L; l++) {
        // ---- phase 1: r, u gates (GEMM over h) ----
        group_wait(g_flagA, fbase, 2 * l + 1);

        float ar[4], au[4], at[4];
#pragma unroll
        for (int i = 0; i < 4; i++) {
            int m = m0 + mt * 4 + i;
            size_t ap = ((size_t)m * L + l) * (size_t)D + d;
            ar[i] = __ldcg(&g_apre0[ap]);
            au[i] = __ldcg(&g_apre1[ap]);
            at[i] = __ldcg(&g_att[m * L + l]);
        }

        float accR[4] = {}, accU[4] = {};
        {
            const float* rowp = g_hB + (size_t)(m0 + m_l) * D + kq;
            float4 v0 = __ldcg((const float4*)rowp);
            float4 v1 = __ldcg((const float4*)rowp + 1);
            hs[0][kq + 0][m_l] = v0.x; hs[0][kq + 1][m_l] = v0.y; hs[0][kq + 2][m_l] = v0.z; hs[0][kq + 3][m_l] = v0.w;
            hs[0][kq + 4][m_l] = v1.x; hs[0][kq + 5][m_l] = v1.y; hs[0][kq + 6][m_l] = v1.z; hs[0][kq + 7][m_l] = v1.w;
            __syncthreads();
            for (int c = 0; c < 16; c++) {
                if (c < 15) {
                    const float* p = rowp + (c + 1) * 32;
                    v0 = __ldcg((const float4*)p);
                    v1 = __ldcg((const float4*)p + 1);
                }
                const int buf = c & 1;
#pragma unroll
                for (int kk = 0; kk < 32; kk++) {
                    float4 hv = *(const float4*)&hs[buf][kk][mt * 4];
                    const float* wrow = ws + (size_t)((c << 5) + kk) * 48;
                    float wr = wrow[dt], wu = wrow[16 + dt];
                    accR[0] += hv.x * wr; accR[1] += hv.y * wr; accR[2] += hv.z * wr; accR[3] += hv.w * wr;
                    accU[0] += hv.x * wu; accU[1] += hv.y * wu; accU[2] += hv.z * wu; accU[3] += hv.w * wu;
                }
                __syncthreads();
                if (c < 15) {
                    const int nbuf = buf ^ 1;
                    hs[nbuf][kq + 0][m_l] = v0.x; hs[nbuf][kq + 1][m_l] = v0.y; hs[nbuf][kq + 2][m_l] = v0.z; hs[nbuf][kq + 3][m_l] = v0.w;
                    hs[nbuf][kq + 4][m_l] = v1.x; hs[nbuf][kq + 5][m_l] = v1.y; hs[nbuf][kq + 6][m_l] = v1.z; hs[nbuf][kq + 7][m_l] = v1.w;
                    __syncthreads();
                }
            }
        }
#pragma unroll
        for (int i = 0; i < 4; i++) {
            int m = m0 + mt * 4 + i;
            float r = sigmoidf_(ar[i] + accR[i]);
            float u = sigmoidf_(au[i] + accU[i]);
            uu[i] = at[i] * u;
            __stcg(&g_rh[(size_t)m * D + d], r * hval[i]);
        }
        group_arrive(g_flagA, bid, 2 * l + 2);

        // ---- phase 2: h_hat (GEMM over r*h), update h ----
        group_wait(g_flagA, fbase, 2 * l + 2);

        float ah[4];
#pragma unroll
        for (int i = 0; i < 4; i++) {
            int m = m0 + mt * 4 + i;
            ah[i] = __ldcg(&g_apre2[((size_t)m * L + l) * (size_t)D + d]);
        }

        float accH[4] = {};
        {
            const float* rowp = g_rh + (size_t)(m0 + m_l) * D + kq;
            float4 v0 = __ldcg((const float4*)rowp);
            float4 v1 = __ldcg((const float4*)rowp + 1);
            hs[0][kq + 0][m_l] = v0.x; hs[0][kq + 1][m_l] = v0.y; hs[0][kq + 2][m_l] = v0.z; hs[0][kq + 3][m_l] = v0.w;
            hs[0][kq + 4][m_l] = v1.x; hs[0][kq + 5][m_l] = v1.y; hs[0][kq + 6][m_l] = v1.z; hs[0][kq + 7][m_l] = v1.w;
            __syncthreads();
            for (int c = 0; c < 16; c++) {
                if (c < 15) {
                    const float* p = rowp + (c + 1) * 32;
                    v0 = __ldcg((const float4*)p);
                    v1 = __ldcg((const float4*)p + 1);
                }
                const int buf = c & 1;
#pragma unroll
                for (int kk = 0; kk < 32; kk++) {
                    float4 hv = *(const float4*)&hs[buf][kk][mt * 4];
                    float wh = ws[(size_t)((c << 5) + kk) * 48 + 32 + dt];
                    accH[0] += hv.x * wh;
                    accH[1] += hv.y * wh;
                    accH[2] += hv.z * wh;
                    accH[3] += hv.w * wh;
                }
                __syncthreads();
                if (c < 15) {
                    const int nbuf = buf ^ 1;
                    hs[nbuf][kq + 0][m_l] = v0.x; hs[nbuf][kq + 1][m_l] = v0.y; hs[nbuf][kq + 2][m_l] = v0.z; hs[nbuf][kq + 3][m_l] = v0.w;
                    hs[nbuf][kq + 4][m_l] = v1.x; hs[nbuf][kq + 5][m_l] = v1.y; hs[nbuf][kq + 6][m_l] = v1.z; hs[nbuf][kq + 7][m_l] = v1.w;
                    __syncthreads();
                }
            }
        }
#pragma unroll
        for (int i = 0; i < 4; i++) {
            int m = m0 + mt * 4 + i;
            float hh = tanhf(ah[i] + accH[i]);
            hval[i] = (1.f - uu[i]) * hval[i] + uu[i] * hh;
            __stcg(&g_hB[(size_t)m * D + d], hval[i]);
        }
        group_arrive(g_flagA, bid, 2 * l + 3);
    }
}

__global__ void copy_out_kernel(float* __restrict__ out)
{
    int i = blockIdx.x * 512 + threadIdx.x;
    out[i] = g_hB[i];
}

// ---------------- launch ----------------
extern "C" void kernel_launch(void* const* d_in, const int* in_sizes, int n_in,
                              void* d_out, int out_size)
{
    const float* session  = (const float*)d_in[0];
    const float* target   = (const float*)d_in[1];
    const float* w        = (const float*)d_in[2];
    const float* gru_wih  = (const float*)d_in[3];
    const float* gru_whh  = (const float*)d_in[4];
    const float* gru_bih  = (const float*)d_in[5];
    const float* gru_bhh  = (const float*)d_in[6];
    const float* reset_w  = (const float*)d_in[7];
    const float* reset_b  = (const float*)d_in[8];
    const float* update_w = (const float*)d_in[9];
    const float* update_b = (const float*)d_in[10];
    const float* hhat_w   = (const float*)d_in[11];
    const float* hhat_b   = (const float*)d_in[12];
    float* out = (float*)d_out;

    const int WS_BYTES = 512 * 48 * sizeof(float);   // 98304
    cudaFuncSetAttribute(gru_kernel,   cudaFuncAttributeMaxDynamicSharedMemorySize, WS_BYTES);
    cudaFuncSetAttribute(augru_kernel, cudaFuncAttributeMaxDynamicSharedMemorySize, WS_BYTES);

    reset_flags_kernel<<<1, 256>>>();
    // 1) x_proj = session @ wih^T + bih   [51200, 1536]
    gemm_tile128<<<dim3(12, 400), 256>>>(session, 0, gru_wih, 512, gru_bih, 0, K3);
    // 2) u = target @ w^T                 [256, 512]
    gemm_tile128<<<dim3(4, 2), 256>>>(target, 0, w, 512, (const float*)nullptr, 1, D);
    // 3) GRU recurrence
    gru_kernel<<<NB, THR, WS_BYTES>>>(gru_whh, gru_bhh);
    // 4) AUGRU x-side pre-projections: s_state @ W[:, D:2D]^T + b
    gemm_tile128<<<dim3(4, 400), 256>>>(session, 1, reset_w  + D, 2 * D, reset_b,  2, D);
    gemm_tile128<<<dim3(4, 400), 256>>>(session, 1, update_w + D, 2 * D, update_b, 3, D);
    gemm_tile128<<<dim3(4, 400), 256>>>(session, 1, hhat_w   + D, 2 * D, hhat_b,   4, D);
    // 5) attention softmax
    attn_kernel<<<B, 256>>>();
    // 6) AUGRU recurrence
    augru_kernel<<<NB, THR, WS_BYTES>>>(reset_w, update_w, hhat_w);
    // 7) output
    copy_out_kernel<<<B, 512>>>(out);
}

// round 5
// speedup vs baseline: 1.5341x; 1.4474x over previous
#include <cuda_runtime.h>
#include <math.h>

#define B 256
#define L 200
#define D 512
#define K3 1536
#define NB 128
#define THR 256
#define WS_STRIDE 50

// ---------------- device scratch ----------------
__device__ float g_xproj[(size_t)B * L * K3];
__device__ float g_sstate[(size_t)B * L * D];
__device__ float g_apre0[(size_t)B * L * D];
__device__ float g_apre1[(size_t)B * L * D];
__device__ float g_apre2[(size_t)B * L * D];
__device__ float g_uvec[B * D];
__device__ float g_att[B * L];
__device__ float g_hA[B * D];
__device__ float g_hB[B * D];
__device__ float g_rh[B * D];

__device__ volatile int g_flagG[NB];
__device__ volatile int g_flagA[NB];

__global__ void reset_flags_kernel()
{
    int i = threadIdx.x;
    if (i < NB) { g_flagG[i] = 0; g_flagA[i] = 0; }
}

__device__ __forceinline__ float sigmoidf_(float x) { return 1.f / (1.f + expf(-x)); }

__device__ __forceinline__ float to_tf32(float x)
{
    unsigned r;
    asm("cvt.rna.tf32.f32 %0, %1;" : "=r"(r) : "f"(x));
    return __uint_as_float(r);
}

__device__ __forceinline__ void mma8(float* c,
                                     unsigned a0, unsigned a1, unsigned a2, unsigned a3,
                                     unsigned b0, unsigned b1)
{
    asm volatile(
        "mma.sync.aligned.m16n8k8.row.col.f32.tf32.tf32.f32 "
        "{%0,%1,%2,%3},{%4,%5,%6,%7},{%8,%9},{%0,%1,%2,%3};\n"
        : "+f"(c[0]), "+f"(c[1]), "+f"(c[2]), "+f"(c[3])
        : "r"(a0), "r"(a1), "r"(a2), "r"(a3), "r"(b0), "r"(b1));
}

// wait until all 32 flags of this m-group reach target
__device__ __forceinline__ void group_wait(volatile int* flags, int base, int target)
{
    if (threadIdx.x < 32) {
        while (true) {
            int v = flags[base + threadIdx.x];
            if (!__any_sync(0xffffffffu, v < target)) break;
            __nanosleep(20);
        }
    }
    __syncthreads();
}

__device__ __forceinline__ void group_arrive(volatile int* flags, int bid, int val)
{
    __syncthreads();
    if (threadIdx.x == 0) {
        __threadfence();
        flags[bid] = val;
    }
}

// ---------------- tf32 GEMM: C[M,N] = A[M,512] * W[N,512]^T (+bias) ----------------
// 128x128 tile, BK=16 double-buffered, 256 threads, warp tile 32x64 via m16n8k8.
__global__ void __launch_bounds__(256) gemm_tile128(
        const float* __restrict__ Aparam, int a_sel,
        const float* __restrict__ W, int ldw,
        const float* __restrict__ bias,
        int c_sel, int Ntot)
{
    const int K = 512;
    const float* A = (a_sel == 0) ? Aparam : g_sstate;
    float* C = (c_sel == 0) ? g_xproj : (c_sel == 1) ? g_uvec :
               (c_sel == 2) ? g_apre0 : (c_sel == 3) ? g_apre1 : g_apre2;

    __shared__ float As[2][16][132];
    __shared__ float Ws[2][16][132];

    const int m0 = blockIdx.y * 128;
    const int n0 = blockIdx.x * 128;
    const int tid = threadIdx.x;
    const int wid = tid >> 5;
    const int lane = tid & 31;
    const int gid = lane >> 2;
    const int tig = lane & 3;
    const int wm = (wid & 3) * 32;
    const int wn = (wid >> 2) * 64;
    const int lr = tid >> 1;
    const int lc = (tid & 1) * 4;

    float acc[2][8][4];
#pragma unroll
    for (int i = 0; i < 2; i++)
#pragma unroll
        for (int j = 0; j < 8; j++)
#pragma unroll
            for (int q = 0; q < 4; q++) acc[i][j][q] = 0.f;

    const float* Abase = A + (size_t)(m0 + lr) * K + lc;
    const float* Wbase = W + (size_t)(n0 + lr) * ldw + lc;

    // prologue: chunk 0
    float4 a0 = *(const float4*)(Abase);
    float4 a1 = *(const float4*)(Abase + 8);
    float4 w0 = *(const float4*)(Wbase);
    float4 w1 = *(const float4*)(Wbase + 8);
    As[0][lc + 0][lr] = to_tf32(a0.x); As[0][lc + 1][lr] = to_tf32(a0.y);
    As[0][lc + 2][lr] = to_tf32(a0.z); As[0][lc + 3][lr] = to_tf32(a0.w);
    As[0][lc + 8][lr] = to_tf32(a1.x); As[0][lc + 9][lr] = to_tf32(a1.y);
    As[0][lc +10][lr] = to_tf32(a1.z); As[0][lc +11][lr] = to_tf32(a1.w);
    Ws[0][lc + 0][lr] = to_tf32(w0.x); Ws[0][lc + 1][lr] = to_tf32(w0.y);
    Ws[0][lc + 2][lr] = to_tf32(w0.z); Ws[0][lc + 3][lr] = to_tf32(w0.w);
    Ws[0][lc + 8][lr] = to_tf32(w1.x); Ws[0][lc + 9][lr] = to_tf32(w1.y);
    Ws[0][lc +10][lr] = to_tf32(w1.z); Ws[0][lc +11][lr] = to_tf32(w1.w);
    __syncthreads();

    for (int c = 0; c < 32; c++) {
        if (c < 31) {
            int k0 = (c + 1) * 16;
            a0 = *(const float4*)(Abase + k0);
            a1 = *(const float4*)(Abase + k0 + 8);
            w0 = *(const float4*)(Wbase + k0);
            w1 = *(const float4*)(Wbase + k0 + 8);
        }
        const int buf = c & 1;
        const unsigned* Au = (const unsigned*)&As[buf][0][0];
        const unsigned* Wu = (const unsigned*)&Ws[buf][0][0];
#pragma unroll
        for (int k8 = 0; k8 < 16; k8 += 8) {
            unsigned af[2][4];
#pragma unroll
            for (int i = 0; i < 2; i++) {
                int mrow = wm + i * 16 + gid;
                af[i][0] = Au[(k8 + tig) * 132 + mrow];
                af[i][1] = Au[(k8 + tig) * 132 + mrow + 8];
                af[i][2] = Au[(k8 + tig + 4) * 132 + mrow];
                af[i][3] = Au[(k8 + tig + 4) * 132 + mrow + 8];
            }
#pragma unroll
            for (int j = 0; j < 8; j++) {
                int ncol = wn + j * 8 + gid;
                unsigned b0 = Wu[(k8 + tig) * 132 + ncol];
                unsigned b1 = Wu[(k8 + tig + 4) * 132 + ncol];
                mma8(acc[0][j], af[0][0], af[0][1], af[0][2], af[0][3], b0, b1);
                mma8(acc[1][j], af[1][0], af[1][1], af[1][2], af[1][3], b0, b1);
            }
        }
        __syncthreads();
        if (c < 31) {
            const int nbuf = buf ^ 1;
            As[nbuf][lc + 0][lr] = to_tf32(a0.x); As[nbuf][lc + 1][lr] = to_tf32(a0.y);
            As[nbuf][lc + 2][lr] = to_tf32(a0.z); As[nbuf][lc + 3][lr] = to_tf32(a0.w);
            As[nbuf][lc + 8][lr] = to_tf32(a1.x); As[nbuf][lc + 9][lr] = to_tf32(a1.y);
            As[nbuf][lc +10][lr] = to_tf32(a1.z); As[nbuf][lc +11][lr] = to_tf32(a1.w);
            Ws[nbuf][lc + 0][lr] = to_tf32(w0.x); Ws[nbuf][lc + 1][lr] = to_tf32(w0.y);
            Ws[nbuf][lc + 2][lr] = to_tf32(w0.z); Ws[nbuf][lc + 3][lr] = to_tf32(w0.w);
            Ws[nbuf][lc + 8][lr] = to_tf32(w1.x); Ws[nbuf][lc + 9][lr] = to_tf32(w1.y);
            Ws[nbuf][lc +10][lr] = to_tf32(w1.z); Ws[nbuf][lc +11][lr] = to_tf32(w1.w);
            __syncthreads();
        }
    }

#pragma unroll
    for (int i = 0; i < 2; i++) {
#pragma unroll
        for (int j = 0; j < 8; j++) {
            int col = n0 + wn + j * 8 + 2 * tig;
            float b0 = bias ? bias[col] : 0.f;
            float b1 = bias ? bias[col + 1] : 0.f;
            int r0 = m0 + wm + i * 16 + gid;
            float2 v0 = make_float2(acc[i][j][0] + b0, acc[i][j][1] + b1);
            float2 v1 = make_float2(acc[i][j][2] + b0, acc[i][j][3] + b1);
            *(float2*)(C + (size_t)r0 * Ntot + col) = v0;
            *(float2*)(C + (size_t)(r0 + 8) * Ntot + col) = v1;
        }
    }
}

// ============ shared helpers for recurrent kernels ============
// dynamic smem layout (floats): ws[512*WS_STRIDE] | hs[2][64][68] | accs[64][52]
#define HS_OFF   (512 * WS_STRIDE)
#define ACC_OFF  (HS_OFF + 2 * 64 * 68)
#define REC_SMEM ((ACC_OFF + 64 * 52) * 4)

// stage one 64-k chunk of src rows [m0..m0+64) into hs buffer (tf32), regs pre-loaded
struct Stage { float4 v[4]; };

__device__ __forceinline__ void stage_load(Stage& s, const float* src, int m0, int m_l, int kq, int k0)
{
    const float4* p = (const float4*)(src + (size_t)(m0 + m_l) * D + k0 + kq);
    s.v[0] = __ldcg(p); s.v[1] = __ldcg(p + 1); s.v[2] = __ldcg(p + 2); s.v[3] = __ldcg(p + 3);
}

__device__ __forceinline__ void stage_store(float* hb, const Stage& s, int m_l, int kq)
{
    const float* f = (const float*)&s.v[0];
#pragma unroll
    for (int j = 0; j < 16; j++)
        hb[(kq + j) * 68 + m_l] = to_tf32(f[j]);
}

// run the K=512 mma loop: per warp one m16 tile (wm), NT n8 tiles at cols colb[t]
template<int NT>
__device__ __forceinline__ void rec_mma(const float* smem, const float* src, int m0,
                                        int m_l, int kq, int gid, int tig, int wm,
                                        const int* colb, float acc[][4])
{
    const float* ws = smem;
    float* hs = (float*)(smem + HS_OFF);
    Stage st;
    stage_load(st, src, m0, m_l, kq, 0);
    stage_store(hs, st, m_l, kq);
    __syncthreads();
    for (int c = 0; c < 8; c++) {
        if (c < 7) stage_load(st, src, m0, m_l, kq, (c + 1) * 64);
        const unsigned* hb = (const unsigned*)(hs + (c & 1) * 64 * 68);
        const unsigned* wu = (const unsigned*)ws;
        const int k0 = c * 64;
#pragma unroll
        for (int kk8 = 0; kk8 < 8; kk8++) {
            int kl = kk8 * 8;
            unsigned a0 = hb[(kl + tig) * 68 + wm + gid];
            unsigned a1 = hb[(kl + tig) * 68 + wm + gid + 8];
            unsigned a2 = hb[(kl + tig + 4) * 68 + wm + gid];
            unsigned a3 = hb[(kl + tig + 4) * 68 + wm + gid + 8];
#pragma unroll
            for (int t = 0; t < NT; t++) {
                unsigned b0 = wu[(k0 + kl + tig) * WS_STRIDE + colb[t] + gid];
                unsigned b1 = wu[(k0 + kl + tig + 4) * WS_STRIDE + colb[t] + gid];
                mma8(acc[t], a0, a1, a2, a3, b0, b1);
            }
        }
        __syncthreads();
        if (c < 7) {
            stage_store(hs + ((c & 1) ^ 1) * 64 * 68, st, m_l, kq);
            __syncthreads();
        }
    }
}

// scatter NT fragment tiles into accs[64][52] at cols fcol[t]
template<int NT>
__device__ __forceinline__ void frag_to_accs(float* smem, int wm, int gid, int tig,
                                             const int* fcol, float acc[][4])
{
    float* accs = smem + ACC_OFF;
#pragma unroll
    for (int t = 0; t < NT; t++) {
        int col = fcol[t] + 2 * tig;
        *(float2*)&accs[(wm + gid) * 52 + col]     = make_float2(acc[t][0], acc[t][1]);
        *(float2*)&accs[(wm + gid + 8) * 52 + col] = make_float2(acc[t][2], acc[t][3]);
    }
    __syncthreads();
}

// ---------------- GRU persistent kernel ----------------
// 128 CTAs = 4 m-groups(64) x 32 d-tiles(16). N = 48 (3 gates x 16 d).
__global__ void __launch_bounds__(THR, 1) gru_kernel(const float* __restrict__ whh,
                                                     const float* __restrict__ bhh)
{
    extern __shared__ float smem[];
    float* ws = smem;
    float* accs = smem + ACC_OFF;

    const int bid = blockIdx.x;
    const int mb = bid >> 5;
    const int m0 = mb * 64;
    const int fbase = mb * 32;
    const int d0 = (bid & 31) * 16;
    const int tid = threadIdx.x;
    const int wid = tid >> 5;
    const int lane = tid & 31;
    const int gid = lane >> 2;
    const int tig = lane & 3;
    const int wm = (wid >> 1) * 16;
    const int nh = wid & 1;
    const int mt = tid >> 4;
    const int dt = tid & 15;
    const int m_l = tid >> 2;
    const int kq = (tid & 3) * 16;
    const int d = d0 + dt;

    int colb[3] = { nh * 24, nh * 24 + 8, nh * 24 + 16 };

    for (int idx = tid; idx < 3 * 512 * 16; idx += THR) {
        int g = idx >> 13;
        int rem = idx & 8191;
        int k = rem >> 4;
        int dd = rem & 15;
        ws[k * WS_STRIDE + g * 16 + dd] = to_tf32(__ldg(whh + (size_t)(g * 512 + d0 + dd) * D + k));
    }
    for (int i = tid; i < 1024; i += THR)
        g_hA[bid * 1024 + i] = 0.f;

    const float bR = bhh[d], bZ = bhh[512 + d], bN = bhh[1024 + d];

    group_arrive(g_flagG, bid, 1);

    for (int l = 0; l < L; l++) {
        const float* __restrict__ hin = (l & 1) ? g_hB : g_hA;
        float* __restrict__ hout = (l & 1) ? g_hA : g_hB;
        group_wait(g_flagG, fbase, l + 1);

        float xr[4], xz[4], xn[4], hp[4];
#pragma unroll
        for (int i = 0; i < 4; i++) {
            int m = m0 + mt * 4 + i;
            size_t xb = ((size_t)m * L + l) * (size_t)K3 + d;
            xr[i] = __ldcg(&g_xproj[xb]);
            xz[i] = __ldcg(&g_xproj[xb + 512]);
            xn[i] = __ldcg(&g_xproj[xb + 1024]);
            hp[i] = __ldcg(hin + (size_t)m * D + d);
        }

        float acc[3][4];
#pragma unroll
        for (int t = 0; t < 3; t++)
#pragma unroll
            for (int q = 0; q < 4; q++) acc[t][q] = 0.f;

        rec_mma<3>(smem, hin, m0, m_l, kq, gid, tig, wm, colb, acc);
        frag_to_accs<3>(smem, wm, gid, tig, colb, acc);

#pragma unroll
        for (int i = 0; i < 4; i++) {
            int m = m0 + mt * 4 + i;
            int ml = mt * 4 + i;
            float r = sigmoidf_(xr[i] + accs[ml * 52 + dt] + bR);
            float z = sigmoidf_(xz[i] + accs[ml * 52 + 16 + dt] + bZ);
            float n = tanhf(xn[i] + r * (accs[ml * 52 + 32 + dt] + bN));
            float hnew = (1.f - z) * n + z * hp[i];
            __stcg(hout + (size_t)m * D + d, hnew);
            __stcg(&g_sstate[((size_t)m * L + l) * (size_t)D + d], hnew);
        }
        group_arrive(g_flagG, bid, l + 2);
    }
}

// ---------------- attention: logits + softmax over L ----------------
__global__ void attn_kernel()
{
    int b = blockIdx.x, tid = threadIdx.x;
    __shared__ float us[D];
    __shared__ float logits[L];
    __shared__ float red[8];
    for (int i = tid; i < D; i += 256) us[i] = g_uvec[b * D + i];
    __syncthreads();
    int wid = tid >> 5, lane = tid & 31;
    for (int l = wid; l < L; l += 8) {
        const float* sp = g_sstate + ((size_t)b * L + l) * D;
        float s = 0.f;
#pragma unroll
        for (int q = 0; q < 16; q++) s += sp[lane + 32 * q] * us[lane + 32 * q];
#pragma unroll
        for (int o = 16; o > 0; o >>= 1) s += __shfl_down_sync(0xffffffffu, s, o);
        if (lane == 0) logits[l] = s;
    }
    __syncthreads();
    float m = -1e30f;
    for (int i = tid; i < L; i += 256) m = fmaxf(m, logits[i]);
#pragma unroll
    for (int o = 16; o > 0; o >>= 1) m = fmaxf(m, __shfl_xor_sync(0xffffffffu, m, o));
    if (lane == 0) red[wid] = m;
    __syncthreads();
    m = red[0];
#pragma unroll
    for (int i = 1; i < 8; i++) m = fmaxf(m, red[i]);
    __syncthreads();
    float s = 0.f;
    for (int i = tid; i < L; i += 256) { float e = expf(logits[i] - m); logits[i] = e; s += e; }
#pragma unroll
    for (int o = 16; o > 0; o >>= 1) s += __shfl_xor_sync(0xffffffffu, s, o);
    if (lane == 0) red[wid] = s;
    __syncthreads();
    s = 0.f;
#pragma unroll
    for (int i = 0; i < 8; i++) s += red[i];
    float inv = 1.f / s;
    for (int i = tid; i < L; i += 256) g_att[b * L + i] = logits[i] * inv;
}

// ---------------- AUGRU persistent kernel ----------------
__global__ void __launch_bounds__(THR, 1) augru_kernel(const float* __restrict__ reset_w,
                                                       const float* __restrict__ update_w,
                                                       const float* __restrict__ hhat_w)
{
    extern __shared__ float smem[];
    float* ws = smem;
    float* accs = smem + ACC_OFF;

    const int bid = blockIdx.x;
    const int mb = bid >> 5;
    const int m0 = mb * 64;
    const int fbase = mb * 32;
    const int d0 = (bid & 31) * 16;
    const int tid = threadIdx.x;
    const int wid = tid >> 5;
    const int lane = tid & 31;
    const int gid = lane >> 2;
    const int tig = lane & 3;
    const int wm1 = (wid >> 1) * 16;      // phase1 m-tile
    const int nh1 = wid & 1;
    const int wm2 = (wid & 3) * 16;       // phase2 m-tile
    const int nh2 = wid >> 2;
    const int mt = tid >> 4;
    const int dt = tid & 15;
    const int m_l = tid >> 2;
    const int kq = (tid & 3) * 16;
    const int d = d0 + dt;

    int colb1[2] = { nh1 * 16, nh1 * 16 + 8 };   // reset (0..15) + update (16..31)
    int colb2[1] = { 32 + nh2 * 8 };             // hhat (32..47)
    int fcol2[1] = { nh2 * 8 };                  // scatter hhat accs to cols 0..15

    for (int idx = tid; idx < 3 * 512 * 16; idx += THR) {
        int g = idx >> 13;
        int rem = idx & 8191;
        int k = rem >> 4;
        int dd = rem & 15;
        const float* src = (g == 0) ? reset_w : (g == 1) ? update_w : hhat_w;
        ws[k * WS_STRIDE + g * 16 + dd] = to_tf32(__ldg(src + (size_t)(d0 + dd) * (2 * D) + k));
    }

    float hval[4], uu[4];
#pragma unroll
    for (int i = 0; i < 4; i++) {
        int m = m0 + mt * 4 + i;
        hval[i] = __ldcg(g_hA + (size_t)m * D + d);
        __stcg(&g_hB[(size_t)m * D + d], hval[i]);
    }
    group_arrive(g_flagA, bid, 1);

    for (int l = 0; l < L; l++) {
        // ---- phase 1: r, u gates (GEMM over h) ----
        group_wait(g_flagA, fbase, 2 * l + 1);

        float ar[4], au[4], at[4];
#pragma unroll
        for (int i = 0; i < 4; i++) {
            int m = m0 + mt * 4 + i;
            size_t ap = ((size_t)m * L + l) * (size_t)D + d;
            ar[i] = __ldcg(&g_apre0[ap]);
            au[i] = __ldcg(&g_apre1[ap]);
            at[i] = __ldcg(&g_att[m * L + l]);
        }

        float acc1[2][4];
#pragma unroll
        for (int t = 0; t < 2; t++)
#pragma unroll
            for (int q = 0; q < 4; q++) acc1[t][q] = 0.f;

        rec_mma<2>(smem, g_hB, m0, m_l, kq, gid, tig, wm1, colb1, acc1);
        frag_to_accs<2>(smem, wm1, gid, tig, colb1, acc1);

#pragma unroll
        for (int i = 0; i < 4; i++) {
            int m = m0 + mt * 4 + i;
            int ml = mt * 4 + i;
            float r = sigmoidf_(ar[i] + accs[ml * 52 + dt]);
            float u = sigmoidf_(au[i] + accs[ml * 52 + 16 + dt]);
            uu[i] = at[i] * u;
            __stcg(&g_rh[(size_t)m * D + d], r * hval[i]);
        }
        group_arrive(g_flagA, bid, 2 * l + 2);

        // ---- phase 2: h_hat (GEMM over r*h), update h ----
        group_wait(g_flagA, fbase, 2 * l + 2);

        float ah[4];
#pragma unroll
        for (int i = 0; i < 4; i++) {
            int m = m0 + mt * 4 + i;
            ah[i] = __ldcg(&g_apre2[((size_t)m * L + l) * (size_t)D + d]);
        }

        float acc2[1][4];
#pragma unroll
        for (int q = 0; q < 4; q++) acc2[0][q] = 0.f;

        rec_mma<1>(smem, g_rh, m0, m_l, kq, gid, tig, wm2, colb2, acc2);
        frag_to_accs<1>(smem, wm2, gid, tig, fcol2, acc2);

#pragma unroll
        for (int i = 0; i < 4; i++) {
            int m = m0 + mt * 4 + i;
            int ml = mt * 4 + i;
            float hh = tanhf(ah[i] + accs[ml * 52 + dt]);
            hval[i] = (1.f - uu[i]) * hval[i] + uu[i] * hh;
            __stcg(&g_hB[(size_t)m * D + d], hval[i]);
        }
        group_arrive(g_flagA, bid, 2 * l + 3);
    }
}

__global__ void copy_out_kernel(float* __restrict__ out)
{
    int i = blockIdx.x * 512 + threadIdx.x;
    out[i] = g_hB[i];
}

// ---------------- launch ----------------
extern "C" void kernel_launch(void* const* d_in, const int* in_sizes, int n_in,
                              void* d_out, int out_size)
{
    const float* session  = (const float*)d_in[0];
    const float* target   = (const float*)d_in[1];
    const float* w        = (const float*)d_in[2];
    const float* gru_wih  = (const float*)d_in[3];
    const float* gru_whh  = (const float*)d_in[4];
    const float* gru_bih  = (const float*)d_in[5];
    const float* gru_bhh  = (const float*)d_in[6];
    const float* reset_w  = (const float*)d_in[7];
    const float* reset_b  = (const float*)d_in[8];
    const float* update_w = (const float*)d_in[9];
    const float* update_b = (const float*)d_in[10];
    const float* hhat_w   = (const float*)d_in[11];
    const float* hhat_b   = (const float*)d_in[12];
    float* out = (float*)d_out;

    cudaFuncSetAttribute(gru_kernel,   cudaFuncAttributeMaxDynamicSharedMemorySize, REC_SMEM);
    cudaFuncSetAttribute(augru_kernel, cudaFuncAttributeMaxDynamicSharedMemorySize, REC_SMEM);

    reset_flags_kernel<<<1, 256>>>();
    // 1) x_proj = session @ wih^T + bih   [51200, 1536]
    gemm_tile128<<<dim3(12, 400), 256>>>(session, 0, gru_wih, 512, gru_bih, 0, K3);
    // 2) u = target @ w^T                 [256, 512]
    gemm_tile128<<<dim3(4, 2), 256>>>(target, 0, w, 512, (const float*)nullptr, 1, D);
    // 3) GRU recurrence
    gru_kernel<<<NB, THR, REC_SMEM>>>(gru_whh, gru_bhh);
    // 4) AUGRU x-side pre-projections: s_state @ W[:, D:2D]^T + b
    gemm_tile128<<<dim3(4, 400), 256>>>(session, 1, reset_w  + D, 2 * D, reset_b,  2, D);
    gemm_tile128<<<dim3(4, 400), 256>>>(session, 1, update_w + D, 2 * D, update_b, 3, D);
    gemm_tile128<<<dim3(4, 400), 256>>>(session, 1, hhat_w   + D, 2 * D, hhat_b,   4, D);
    // 5) attention softmax
    attn_kernel<<<B, 256>>>();
    // 6) AUGRU recurrence
    augru_kernel<<<NB, THR, REC_SMEM>>>(reset_w, update_w, hhat_w);
    // 7) output
    copy_out_kernel<<<B, 512>>>(out);
}

// round 6
// speedup vs baseline: 1.5387x; 1.0030x over previous
#include <cuda_runtime.h>
#include <math.h>

#define B 256
#define L 200
#define D 512
#define K3 1536
#define NB 128
#define THR 256
#define WS_STRIDE 50

// ---------------- device scratch ----------------
__device__ float g_xproj[(size_t)B * L * K3];
__device__ float g_sstate[(size_t)B * L * D];
__device__ float g_apre0[(size_t)B * L * D];
__device__ float g_apre1[(size_t)B * L * D];
__device__ float g_apre2[(size_t)B * L * D];
__device__ float g_uvec[B * D];
__device__ float g_att[B * L];
__device__ float g_hA[B * D];
__device__ float g_hB[B * D];
__device__ float g_rh[B * D];

__device__ volatile int g_flagG[NB];
__device__ volatile int g_flagA[NB];

__global__ void reset_flags_kernel()
{
    int i = threadIdx.x;
    if (i < NB) { g_flagG[i] = 0; g_flagA[i] = 0; }
}

__device__ __forceinline__ float sigmoidf_(float x) { return 1.f / (1.f + expf(-x)); }

__device__ __forceinline__ float to_tf32(float x)
{
    unsigned r;
    asm("cvt.rna.tf32.f32 %0, %1;" : "=r"(r) : "f"(x));
    return __uint_as_float(r);
}

__device__ __forceinline__ void mma8(float* c,
                                     unsigned a0, unsigned a1, unsigned a2, unsigned a3,
                                     unsigned b0, unsigned b1)
{
    asm volatile(
        "mma.sync.aligned.m16n8k8.row.col.f32.tf32.tf32.f32 "
        "{%0,%1,%2,%3},{%4,%5,%6,%7},{%8,%9},{%0,%1,%2,%3};\n"
        : "+f"(c[0]), "+f"(c[1]), "+f"(c[2]), "+f"(c[3])
        : "r"(a0), "r"(a1), "r"(a2), "r"(a3), "r"(b0), "r"(b1));
}

// wait until all 32 flags of this m-group reach target
__device__ __forceinline__ void group_wait(volatile int* flags, int base, int target)
{
    if (threadIdx.x < 32) {
        while (true) {
            int v = flags[base + threadIdx.x];
            if (!__any_sync(0xffffffffu, v < target)) break;
            __nanosleep(20);
        }
    }
    __syncthreads();
}

__device__ __forceinline__ void group_arrive(volatile int* flags, int bid, int val)
{
    __syncthreads();
    if (threadIdx.x == 0) {
        __threadfence();
        flags[bid] = val;
    }
}

// ---------------- tf32 GEMM: C[M,N] = A[M,512] * W[N,512]^T (+bias) ----------------
// 128x128 tile, BK=16 double-buffered, 256 threads, warp tile 32x64 via m16n8k8.
__global__ void __launch_bounds__(256) gemm_tile128(
        const float* __restrict__ Aparam, int a_sel,
        const float* __restrict__ W, int ldw,
        const float* __restrict__ bias,
        int c_sel, int Ntot)
{
    const int K = 512;
    const float* A = (a_sel == 0) ? Aparam : g_sstate;
    float* C = (c_sel == 0) ? g_xproj : (c_sel == 1) ? g_uvec :
               (c_sel == 2) ? g_apre0 : (c_sel == 3) ? g_apre1 : g_apre2;

    __shared__ float As[2][16][132];
    __shared__ float Ws[2][16][132];

    const int m0 = blockIdx.y * 128;
    const int n0 = blockIdx.x * 128;
    const int tid = threadIdx.x;
    const int wid = tid >> 5;
    const int lane = tid & 31;
    const int gid = lane >> 2;
    const int tig = lane & 3;
    const int wm = (wid & 3) * 32;
    const int wn = (wid >> 2) * 64;
    const int lr = tid >> 1;
    const int lc = (tid & 1) * 4;

    float acc[2][8][4];
#pragma unroll
    for (int i = 0; i < 2; i++)
#pragma unroll
        for (int j = 0; j < 8; j++)
#pragma unroll
            for (int q = 0; q < 4; q++) acc[i][j][q] = 0.f;

    const float* Abase = A + (size_t)(m0 + lr) * K + lc;
    const float* Wbase = W + (size_t)(n0 + lr) * ldw + lc;

    // prologue: chunk 0
    float4 a0 = *(const float4*)(Abase);
    float4 a1 = *(const float4*)(Abase + 8);
    float4 w0 = *(const float4*)(Wbase);
    float4 w1 = *(const float4*)(Wbase + 8);
    As[0][lc + 0][lr] = to_tf32(a0.x); As[0][lc + 1][lr] = to_tf32(a0.y);
    As[0][lc + 2][lr] = to_tf32(a0.z); As[0][lc + 3][lr] = to_tf32(a0.w);
    As[0][lc + 8][lr] = to_tf32(a1.x); As[0][lc + 9][lr] = to_tf32(a1.y);
    As[0][lc +10][lr] = to_tf32(a1.z); As[0][lc +11][lr] = to_tf32(a1.w);
    Ws[0][lc + 0][lr] = to_tf32(w0.x); Ws[0][lc + 1][lr] = to_tf32(w0.y);
    Ws[0][lc + 2][lr] = to_tf32(w0.z); Ws[0][lc + 3][lr] = to_tf32(w0.w);
    Ws[0][lc + 8][lr] = to_tf32(w1.x); Ws[0][lc + 9][lr] = to_tf32(w1.y);
    Ws[0][lc +10][lr] = to_tf32(w1.z); Ws[0][lc +11][lr] = to_tf32(w1.w);
    __syncthreads();

    for (int c = 0; c < 32; c++) {
        if (c < 31) {
            int k0 = (c + 1) * 16;
            a0 = *(const float4*)(Abase + k0);
            a1 = *(const float4*)(Abase + k0 + 8);
            w0 = *(const float4*)(Wbase + k0);
            w1 = *(const float4*)(Wbase + k0 + 8);
        }
        const int buf = c & 1;
        const unsigned* Au = (const unsigned*)&As[buf][0][0];
        const unsigned* Wu = (const unsigned*)&Ws[buf][0][0];
#pragma unroll
        for (int k8 = 0; k8 < 16; k8 += 8) {
            unsigned af[2][4];
#pragma unroll
            for (int i = 0; i < 2; i++) {
                int mrow = wm + i * 16 + gid;
                af[i][0] = Au[(k8 + tig) * 132 + mrow];
                af[i][1] = Au[(k8 + tig) * 132 + mrow + 8];
                af[i][2] = Au[(k8 + tig + 4) * 132 + mrow];
                af[i][3] = Au[(k8 + tig + 4) * 132 + mrow + 8];
            }
#pragma unroll
            for (int j = 0; j < 8; j++) {
                int ncol = wn + j * 8 + gid;
                unsigned b0 = Wu[(k8 + tig) * 132 + ncol];
                unsigned b1 = Wu[(k8 + tig + 4) * 132 + ncol];
                mma8(acc[0][j], af[0][0], af[0][1], af[0][2], af[0][3], b0, b1);
                mma8(acc[1][j], af[1][0], af[1][1], af[1][2], af[1][3], b0, b1);
            }
        }
        __syncthreads();
        if (c < 31) {
            const int nbuf = buf ^ 1;
            As[nbuf][lc + 0][lr] = to_tf32(a0.x); As[nbuf][lc + 1][lr] = to_tf32(a0.y);
            As[nbuf][lc + 2][lr] = to_tf32(a0.z); As[nbuf][lc + 3][lr] = to_tf32(a0.w);
            As[nbuf][lc + 8][lr] = to_tf32(a1.x); As[nbuf][lc + 9][lr] = to_tf32(a1.y);
            As[nbuf][lc +10][lr] = to_tf32(a1.z); As[nbuf][lc +11][lr] = to_tf32(a1.w);
            Ws[nbuf][lc + 0][lr] = to_tf32(w0.x); Ws[nbuf][lc + 1][lr] = to_tf32(w0.y);
            Ws[nbuf][lc + 2][lr] = to_tf32(w0.z); Ws[nbuf][lc + 3][lr] = to_tf32(w0.w);
            Ws[nbuf][lc + 8][lr] = to_tf32(w1.x); Ws[nbuf][lc + 9][lr] = to_tf32(w1.y);
            Ws[nbuf][lc +10][lr] = to_tf32(w1.z); Ws[nbuf][lc +11][lr] = to_tf32(w1.w);
            __syncthreads();
        }
    }

#pragma unroll
    for (int i = 0; i < 2; i++) {
#pragma unroll
        for (int j = 0; j < 8; j++) {
            int col = n0 + wn + j * 8 + 2 * tig;
            float b0 = bias ? bias[col] : 0.f;
            float b1 = bias ? bias[col + 1] : 0.f;
            int r0 = m0 + wm + i * 16 + gid;
            float2 v0 = make_float2(acc[i][j][0] + b0, acc[i][j][1] + b1);
            float2 v1 = make_float2(acc[i][j][2] + b0, acc[i][j][3] + b1);
            *(float2*)(C + (size_t)r0 * Ntot + col) = v0;
            *(float2*)(C + (size_t)(r0 + 8) * Ntot + col) = v1;
        }
    }
}

// ============ shared helpers for recurrent kernels ============
// dynamic smem layout (floats): ws[512*WS_STRIDE] | hs[2][64][68] | accs[64][52]
#define HS_OFF   (512 * WS_STRIDE)
#define ACC_OFF  (HS_OFF + 2 * 64 * 68)
#define REC_SMEM ((ACC_OFF + 64 * 52) * 4)

// stage one 64-k chunk of src rows [m0..m0+64) into hs buffer (tf32), regs pre-loaded
struct Stage { float4 v[4]; };

__device__ __forceinline__ void stage_load(Stage& s, const float* src, int m0, int m_l, int kq, int k0)
{
    const float4* p = (const float4*)(src + (size_t)(m0 + m_l) * D + k0 + kq);
    s.v[0] = __ldcg(p); s.v[1] = __ldcg(p + 1); s.v[2] = __ldcg(p + 2); s.v[3] = __ldcg(p + 3);
}

__device__ __forceinline__ void stage_store(float* hb, const Stage& s, int m_l, int kq)
{
    const float* f = (const float*)&s.v[0];
#pragma unroll
    for (int j = 0; j < 16; j++)
        hb[(kq + j) * 68 + m_l] = to_tf32(f[j]);
}

// run the K=512 mma loop: per warp one m16 tile (wm), NT n8 tiles at cols colb[t]
template<int NT>
__device__ __forceinline__ void rec_mma(const float* smem, const float* src, int m0,
                                        int m_l, int kq, int gid, int tig, int wm,
                                        const int* colb, float acc[][4])
{
    const float* ws = smem;
    float* hs = (float*)(smem + HS_OFF);
    Stage st;
    stage_load(st, src, m0, m_l, kq, 0);
    stage_store(hs, st, m_l, kq);
    __syncthreads();
    for (int c = 0; c < 8; c++) {
        if (c < 7) stage_load(st, src, m0, m_l, kq, (c + 1) * 64);
        const unsigned* hb = (const unsigned*)(hs + (c & 1) * 64 * 68);
        const unsigned* wu = (const unsigned*)ws;
        const int k0 = c * 64;
#pragma unroll
        for (int kk8 = 0; kk8 < 8; kk8++) {
            int kl = kk8 * 8;
            unsigned a0 = hb[(kl + tig) * 68 + wm + gid];
            unsigned a1 = hb[(kl + tig) * 68 + wm + gid + 8];
            unsigned a2 = hb[(kl + tig + 4) * 68 + wm + gid];
            unsigned a3 = hb[(kl + tig + 4) * 68 + wm + gid + 8];
#pragma unroll
            for (int t = 0; t < NT; t++) {
                unsigned b0 = wu[(k0 + kl + tig) * WS_STRIDE + colb[t] + gid];
                unsigned b1 = wu[(k0 + kl + tig + 4) * WS_STRIDE + colb[t] + gid];
                mma8(acc[t], a0, a1, a2, a3, b0, b1);
            }
        }
        __syncthreads();
        if (c < 7) {
            stage_store(hs + ((c & 1) ^ 1) * 64 * 68, st, m_l, kq);
            __syncthreads();
        }
    }
}

// scatter NT fragment tiles into accs[64][52] at cols fcol[t]
template<int NT>
__device__ __forceinline__ void frag_to_accs(float* smem, int wm, int gid, int tig,
                                             const int* fcol, float acc[][4])
{
    float* accs = smem + ACC_OFF;
#pragma unroll
    for (int t = 0; t < NT; t++) {
        int col = fcol[t] + 2 * tig;
        *(float2*)&accs[(wm + gid) * 52 + col]     = make_float2(acc[t][0], acc[t][1]);
        *(float2*)&accs[(wm + gid + 8) * 52 + col] = make_float2(acc[t][2], acc[t][3]);
    }
    __syncthreads();
}

// ---------------- GRU persistent kernel ----------------
// 128 CTAs = 4 m-groups(64) x 32 d-tiles(16). N = 48 (3 gates x 16 d).
__global__ void __launch_bounds__(THR, 1) gru_kernel(const float* __restrict__ whh,
                                                     const float* __restrict__ bhh)
{
    extern __shared__ float smem[];
    float* ws = smem;
    float* accs = smem + ACC_OFF;

    const int bid = blockIdx.x;
    const int mb = bid >> 5;
    const int m0 = mb * 64;
    const int fbase = mb * 32;
    const int d0 = (bid & 31) * 16;
    const int tid = threadIdx.x;
    const int wid = tid >> 5;
    const int lane = tid & 31;
    const int gid = lane >> 2;
    const int tig = lane & 3;
    const int wm = (wid >> 1) * 16;
    const int nh = wid & 1;
    const int mt = tid >> 4;
    const int dt = tid & 15;
    const int m_l = tid >> 2;
    const int kq = (tid & 3) * 16;
    const int d = d0 + dt;

    int colb[3] = { nh * 24, nh * 24 + 8, nh * 24 + 16 };

    for (int idx = tid; idx < 3 * 512 * 16; idx += THR) {
        int g = idx >> 13;
        int rem = idx & 8191;
        int k = rem >> 4;
        int dd = rem & 15;
        ws[k * WS_STRIDE + g * 16 + dd] = to_tf32(__ldg(whh + (size_t)(g * 512 + d0 + dd) * D + k));
    }
    for (int i = tid; i < 1024; i += THR)
        g_hA[bid * 1024 + i] = 0.f;

    const float bR = bhh[d], bZ = bhh[512 + d], bN = bhh[1024 + d];

    group_arrive(g_flagG, bid, 1);

    for (int l = 0; l < L; l++) {
        const float* __restrict__ hin = (l & 1) ? g_hB : g_hA;
        float* __restrict__ hout = (l & 1) ? g_hA : g_hB;
        group_wait(g_flagG, fbase, l + 1);

        float xr[4], xz[4], xn[4], hp[4];
#pragma unroll
        for (int i = 0; i < 4; i++) {
            int m = m0 + mt * 4 + i;
            size_t xb = ((size_t)m * L + l) * (size_t)K3 + d;
            xr[i] = __ldcg(&g_xproj[xb]);
            xz[i] = __ldcg(&g_xproj[xb + 512]);
            xn[i] = __ldcg(&g_xproj[xb + 1024]);
            hp[i] = __ldcg(hin + (size_t)m * D + d);
        }

        float acc[3][4];
#pragma unroll
        for (int t = 0; t < 3; t++)
#pragma unroll
            for (int q = 0; q < 4; q++) acc[t][q] = 0.f;

        rec_mma<3>(smem, hin, m0, m_l, kq, gid, tig, wm, colb, acc);
        frag_to_accs<3>(smem, wm, gid, tig, colb, acc);

#pragma unroll
        for (int i = 0; i < 4; i++) {
            int m = m0 + mt * 4 + i;
            int ml = mt * 4 + i;
            float r = sigmoidf_(xr[i] + accs[ml * 52 + dt] + bR);
            float z = sigmoidf_(xz[i] + accs[ml * 52 + 16 + dt] + bZ);
            float n = tanhf(xn[i] + r * (accs[ml * 52 + 32 + dt] + bN));
            float hnew = (1.f - z) * n + z * hp[i];
            __stcg(hout + (size_t)m * D + d, hnew);
            __stcg(&g_sstate[((size_t)m * L + l) * (size_t)D + d], hnew);
        }
        group_arrive(g_flagG, bid, l + 2);
    }
}

// ---------------- attention: logits + softmax over L ----------------
__global__ void attn_kernel()
{
    int b = blockIdx.x, tid = threadIdx.x;
    __shared__ float us[D];
    __shared__ float logits[L];
    __shared__ float red[8];
    for (int i = tid; i < D; i += 256) us[i] = g_uvec[b * D + i];
    __syncthreads();
    int wid = tid >> 5, lane = tid & 31;
    for (int l = wid; l < L; l += 8) {
        const float* sp = g_sstate + ((size_t)b * L + l) * D;
        float s = 0.f;
#pragma unroll
        for (int q = 0; q < 16; q++) s += sp[lane + 32 * q] * us[lane + 32 * q];
#pragma unroll
        for (int o = 16; o > 0; o >>= 1) s += __shfl_down_sync(0xffffffffu, s, o);
        if (lane == 0) logits[l] = s;
    }
    __syncthreads();
    float m = -1e30f;
    for (int i = tid; i < L; i += 256) m = fmaxf(m, logits[i]);
#pragma unroll
    for (int o = 16; o > 0; o >>= 1) m = fmaxf(m, __shfl_xor_sync(0xffffffffu, m, o));
    if (lane == 0) red[wid] = m;
    __syncthreads();
    m = red[0];
#pragma unroll
    for (int i = 1; i < 8; i++) m = fmaxf(m, red[i]);
    __syncthreads();
    float s = 0.f;
    for (int i = tid; i < L; i += 256) { float e = expf(logits[i] - m); logits[i] = e; s += e; }
#pragma unroll
    for (int o = 16; o > 0; o >>= 1) s += __shfl_xor_sync(0xffffffffu, s, o);
    if (lane == 0) red[wid] = s;
    __syncthreads();
    s = 0.f;
#pragma unroll
    for (int i = 0; i < 8; i++) s += red[i];
    float inv = 1.f / s;
    for (int i = tid; i < L; i += 256) g_att[b * L + i] = logits[i] * inv;
}

// ---------------- AUGRU persistent kernel ----------------
__global__ void __launch_bounds__(THR, 1) augru_kernel(const float* __restrict__ reset_w,
                                                       const float* __restrict__ update_w,
                                                       const float* __restrict__ hhat_w)
{
    extern __shared__ float smem[];
    float* ws = smem;
    float* accs = smem + ACC_OFF;

    const int bid = blockIdx.x;
    const int mb = bid >> 5;
    const int m0 = mb * 64;
    const int fbase = mb * 32;
    const int d0 = (bid & 31) * 16;
    const int tid = threadIdx.x;
    const int wid = tid >> 5;
    const int lane = tid & 31;
    const int gid = lane >> 2;
    const int tig = lane & 3;
    const int wm1 = (wid >> 1) * 16;      // phase1 m-tile
    const int nh1 = wid & 1;
    const int wm2 = (wid & 3) * 16;       // phase2 m-tile
    const int nh2 = wid >> 2;
    const int mt = tid >> 4;
    const int dt = tid & 15;
    const int m_l = tid >> 2;
    const int kq = (tid & 3) * 16;
    const int d = d0 + dt;

    int colb1[2] = { nh1 * 16, nh1 * 16 + 8 };   // reset (0..15) + update (16..31)
    int colb2[1] = { 32 + nh2 * 8 };             // hhat (32..47)
    int fcol2[1] = { nh2 * 8 };                  // scatter hhat accs to cols 0..15

    for (int idx = tid; idx < 3 * 512 * 16; idx += THR) {
        int g = idx >> 13;
        int rem = idx & 8191;
        int k = rem >> 4;
        int dd = rem & 15;
        const float* src = (g == 0) ? reset_w : (g == 1) ? update_w : hhat_w;
        ws[k * WS_STRIDE + g * 16 + dd] = to_tf32(__ldg(src + (size_t)(d0 + dd) * (2 * D) + k));
    }

    float hval[4], uu[4];
#pragma unroll
    for (int i = 0; i < 4; i++) {
        int m = m0 + mt * 4 + i;
        hval[i] = __ldcg(g_hA + (size_t)m * D + d);
        __stcg(&g_hB[(size_t)m * D + d], hval[i]);
    }
    group_arrive(g_flagA, bid, 1);

    for (int l = 0; l < L; l++) {
        // ---- phase 1: r, u gates (GEMM over h) ----
        group_wait(g_flagA, fbase, 2 * l + 1);

        float ar[4], au[4], at[4];
#pragma unroll
        for (int i = 0; i < 4; i++) {
            int m = m0 + mt * 4 + i;
            size_t ap = ((size_t)m * L + l) * (size_t)D + d;
            ar[i] = __ldcg(&g_apre0[ap]);
            au[i] = __ldcg(&g_apre1[ap]);
            at[i] = __ldcg(&g_att[m * L + l]);
        }

        float acc1[2][4];
#pragma unroll
        for (int t = 0; t < 2; t++)
#pragma unroll
            for (int q = 0; q < 4; q++) acc1[t][q] = 0.f;

        rec_mma<2>(smem, g_hB, m0, m_l, kq, gid, tig, wm1, colb1, acc1);
        frag_to_accs<2>(smem, wm1, gid, tig, colb1, acc1);

#pragma unroll
        for (int i = 0; i < 4; i++) {
            int m = m0 + mt * 4 + i;
            int ml = mt * 4 + i;
            float r = sigmoidf_(ar[i] + accs[ml * 52 + dt]);
            float u = sigmoidf_(au[i] + accs[ml * 52 + 16 + dt]);
            uu[i] = at[i] * u;
            __stcg(&g_rh[(size_t)m * D + d], r * hval[i]);
        }
        group_arrive(g_flagA, bid, 2 * l + 2);

        // ---- phase 2: h_hat (GEMM over r*h), update h ----
        group_wait(g_flagA, fbase, 2 * l + 2);

        float ah[4];
#pragma unroll
        for (int i = 0; i < 4; i++) {
            int m = m0 + mt * 4 + i;
            ah[i] = __ldcg(&g_apre2[((size_t)m * L + l) * (size_t)D + d]);
        }

        float acc2[1][4];
#pragma unroll
        for (int q = 0; q < 4; q++) acc2[0][q] = 0.f;

        rec_mma<1>(smem, g_rh, m0, m_l, kq, gid, tig, wm2, colb2, acc2);
        frag_to_accs<1>(smem, wm2, gid, tig, fcol2, acc2);

#pragma unroll
        for (int i = 0; i < 4; i++) {
            int m = m0 + mt * 4 + i;
            int ml = mt * 4 + i;
            float hh = tanhf(ah[i] + accs[ml * 52 + dt]);
            hval[i] = (1.f - uu[i]) * hval[i] + uu[i] * hh;
            __stcg(&g_hB[(size_t)m * D + d], hval[i]);
        }
        group_arrive(g_flagA, bid, 2 * l + 3);
    }
}

__global__ void copy_out_kernel(float* __restrict__ out)
{
    int i = blockIdx.x * 512 + threadIdx.x;
    out[i] = g_hB[i];
}

// ---------------- launch ----------------
extern "C" void kernel_launch(void* const* d_in, const int* in_sizes, int n_in,
                              void* d_out, int out_size)
{
    const float* session  = (const float*)d_in[0];
    const float* target   = (const float*)d_in[1];
    const float* w        = (const float*)d_in[2];
    const float* gru_wih  = (const float*)d_in[3];
    const float* gru_whh  = (const float*)d_in[4];
    const float* gru_bih  = (const float*)d_in[5];
    const float* gru_bhh  = (const float*)d_in[6];
    const float* reset_w  = (const float*)d_in[7];
    const float* reset_b  = (const float*)d_in[8];
    const float* update_w = (const float*)d_in[9];
    const float* update_b = (const float*)d_in[10];
    const float* hhat_w   = (const float*)d_in[11];
    const float* hhat_b   = (const float*)d_in[12];
    float* out = (float*)d_out;

    cudaFuncSetAttribute(gru_kernel,   cudaFuncAttributeMaxDynamicSharedMemorySize, REC_SMEM);
    cudaFuncSetAttribute(augru_kernel, cudaFuncAttributeMaxDynamicSharedMemorySize, REC_SMEM);

    reset_flags_kernel<<<1, 256>>>();
    // 1) x_proj = session @ wih^T + bih   [51200, 1536]
    gemm_tile128<<<dim3(12, 400), 256>>>(session, 0, gru_wih, 512, gru_bih, 0, K3);
    // 2) u = target @ w^T                 [256, 512]
    gemm_tile128<<<dim3(4, 2), 256>>>(target, 0, w, 512, (const float*)nullptr, 1, D);
    // 3) GRU recurrence
    gru_kernel<<<NB, THR, REC_SMEM>>>(gru_whh, gru_bhh);
    // 4) AUGRU x-side pre-projections: s_state @ W[:, D:2D]^T + b
    gemm_tile128<<<dim3(4, 400), 256>>>(session, 1, reset_w  + D, 2 * D, reset_b,  2, D);
    gemm_tile128<<<dim3(4, 400), 256>>>(session, 1, update_w + D, 2 * D, update_b, 3, D);
    gemm_tile128<<<dim3(4, 400), 256>>>(session, 1, hhat_w   + D, 2 * D, hhat_b,   4, D);
    // 5) attention softmax
    attn_kernel<<<B, 256>>>();
    // 6) AUGRU recurrence
    augru_kernel<<<NB, THR, REC_SMEM>>>(reset_w, update_w, hhat_w);
    // 7) output
    copy_out_kernel<<<B, 512>>>(out);
}

// round 7
// speedup vs baseline: 1.5604x; 1.0141x over previous
#include <cuda_runtime.h>
#include <math.h>

#define B 256
#define L 200
#define D 512
#define K3 1536
#define NB 128
#define THR 256
#define WS_STRIDE 50

// ---------------- device scratch ----------------
__device__ float g_xproj[(size_t)B * L * K3];
__device__ float g_sstate[(size_t)B * L * D];
__device__ float g_apre0[(size_t)B * L * D];
__device__ float g_apre1[(size_t)B * L * D];
__device__ float g_apre2[(size_t)B * L * D];
__device__ float g_uvec[B * D];
__device__ float g_att[B * L];
__device__ float g_hA[B * D];
__device__ float g_hB[B * D];
__device__ float g_rh[B * D];

__device__ volatile int g_flagG[NB];
__device__ volatile int g_flagA[NB];

__global__ void reset_flags_kernel()
{
    int i = threadIdx.x;
    if (i < NB) { g_flagG[i] = 0; g_flagA[i] = 0; }
}

__device__ __forceinline__ float sigmoidf_(float x) { return 1.f / (1.f + expf(-x)); }

__device__ __forceinline__ float to_tf32(float x)
{
    unsigned r;
    asm("cvt.rna.tf32.f32 %0, %1;" : "=r"(r) : "f"(x));
    return __uint_as_float(r);
}

__device__ __forceinline__ void mma8(float* c,
                                     unsigned a0, unsigned a1, unsigned a2, unsigned a3,
                                     unsigned b0, unsigned b1)
{
    asm volatile(
        "mma.sync.aligned.m16n8k8.row.col.f32.tf32.tf32.f32 "
        "{%0,%1,%2,%3},{%4,%5,%6,%7},{%8,%9},{%0,%1,%2,%3};\n"
        : "+f"(c[0]), "+f"(c[1]), "+f"(c[2]), "+f"(c[3])
        : "r"(a0), "r"(a1), "r"(a2), "r"(a3), "r"(b0), "r"(b1));
}

// wait until all 32 flags of this m-group reach target
__device__ __forceinline__ void group_wait(volatile int* flags, int base, int target)
{
    if (threadIdx.x < 32) {
        while (true) {
            int v = flags[base + threadIdx.x];
            if (!__any_sync(0xffffffffu, v < target)) break;
            __nanosleep(20);
        }
    }
    __syncthreads();
}

__device__ __forceinline__ void group_arrive(volatile int* flags, int bid, int val)
{
    __syncthreads();
    if (threadIdx.x == 0) {
        __threadfence();
        flags[bid] = val;
    }
}

// ---------------- tf32 GEMM: C[M,N] = A[M,512] * W[N,512]^T (+bias) ----------------
// 128x128 tile, BK=16 double-buffered, 256 threads, warp tile 32x64 via m16n8k8.
__global__ void __launch_bounds__(256) gemm_tile128(
        const float* __restrict__ Aparam, int a_sel,
        const float* __restrict__ W, int ldw,
        const float* __restrict__ bias,
        int c_sel, int Ntot)
{
    const int K = 512;
    const float* A = (a_sel == 0) ? Aparam : g_sstate;
    float* C = (c_sel == 0) ? g_xproj : (c_sel == 1) ? g_uvec :
               (c_sel == 2) ? g_apre0 : (c_sel == 3) ? g_apre1 : g_apre2;

    __shared__ float As[2][16][132];
    __shared__ float Ws[2][16][132];

    const int m0 = blockIdx.y * 128;
    const int n0 = blockIdx.x * 128;
    const int tid = threadIdx.x;
    const int wid = tid >> 5;
    const int lane = tid & 31;
    const int gid = lane >> 2;
    const int tig = lane & 3;
    const int wm = (wid & 3) * 32;
    const int wn = (wid >> 2) * 64;
    const int lr = tid >> 1;
    const int lc = (tid & 1) * 4;

    float acc[2][8][4];
#pragma unroll
    for (int i = 0; i < 2; i++)
#pragma unroll
        for (int j = 0; j < 8; j++)
#pragma unroll
            for (int q = 0; q < 4; q++) acc[i][j][q] = 0.f;

    const float* Abase = A + (size_t)(m0 + lr) * K + lc;
    const float* Wbase = W + (size_t)(n0 + lr) * ldw + lc;

    // prologue: chunk 0
    float4 a0 = *(const float4*)(Abase);
    float4 a1 = *(const float4*)(Abase + 8);
    float4 w0 = *(const float4*)(Wbase);
    float4 w1 = *(const float4*)(Wbase + 8);
    As[0][lc + 0][lr] = to_tf32(a0.x); As[0][lc + 1][lr] = to_tf32(a0.y);
    As[0][lc + 2][lr] = to_tf32(a0.z); As[0][lc + 3][lr] = to_tf32(a0.w);
    As[0][lc + 8][lr] = to_tf32(a1.x); As[0][lc + 9][lr] = to_tf32(a1.y);
    As[0][lc +10][lr] = to_tf32(a1.z); As[0][lc +11][lr] = to_tf32(a1.w);
    Ws[0][lc + 0][lr] = to_tf32(w0.x); Ws[0][lc + 1][lr] = to_tf32(w0.y);
    Ws[0][lc + 2][lr] = to_tf32(w0.z); Ws[0][lc + 3][lr] = to_tf32(w0.w);
    Ws[0][lc + 8][lr] = to_tf32(w1.x); Ws[0][lc + 9][lr] = to_tf32(w1.y);
    Ws[0][lc +10][lr] = to_tf32(w1.z); Ws[0][lc +11][lr] = to_tf32(w1.w);
    __syncthreads();

    for (int c = 0; c < 32; c++) {
        if (c < 31) {
            int k0 = (c + 1) * 16;
            a0 = *(const float4*)(Abase + k0);
            a1 = *(const float4*)(Abase + k0 + 8);
            w0 = *(const float4*)(Wbase + k0);
            w1 = *(const float4*)(Wbase + k0 + 8);
        }
        const int buf = c & 1;
        const unsigned* Au = (const unsigned*)&As[buf][0][0];
        const unsigned* Wu = (const unsigned*)&Ws[buf][0][0];
#pragma unroll
        for (int k8 = 0; k8 < 16; k8 += 8) {
            unsigned af[2][4];
#pragma unroll
            for (int i = 0; i < 2; i++) {
                int mrow = wm + i * 16 + gid;
                af[i][0] = Au[(k8 + tig) * 132 + mrow];
                af[i][1] = Au[(k8 + tig) * 132 + mrow + 8];
                af[i][2] = Au[(k8 + tig + 4) * 132 + mrow];
                af[i][3] = Au[(k8 + tig + 4) * 132 + mrow + 8];
            }
#pragma unroll
            for (int j = 0; j < 8; j++) {
                int ncol = wn + j * 8 + gid;
                unsigned b0 = Wu[(k8 + tig) * 132 + ncol];
                unsigned b1 = Wu[(k8 + tig + 4) * 132 + ncol];
                mma8(acc[0][j], af[0][0], af[0][1], af[0][2], af[0][3], b0, b1);
                mma8(acc[1][j], af[1][0], af[1][1], af[1][2], af[1][3], b0, b1);
            }
        }
        __syncthreads();
        if (c < 31) {
            const int nbuf = buf ^ 1;
            As[nbuf][lc + 0][lr] = to_tf32(a0.x); As[nbuf][lc + 1][lr] = to_tf32(a0.y);
            As[nbuf][lc + 2][lr] = to_tf32(a0.z); As[nbuf][lc + 3][lr] = to_tf32(a0.w);
            As[nbuf][lc + 8][lr] = to_tf32(a1.x); As[nbuf][lc + 9][lr] = to_tf32(a1.y);
            As[nbuf][lc +10][lr] = to_tf32(a1.z); As[nbuf][lc +11][lr] = to_tf32(a1.w);
            Ws[nbuf][lc + 0][lr] = to_tf32(w0.x); Ws[nbuf][lc + 1][lr] = to_tf32(w0.y);
            Ws[nbuf][lc + 2][lr] = to_tf32(w0.z); Ws[nbuf][lc + 3][lr] = to_tf32(w0.w);
            Ws[nbuf][lc + 8][lr] = to_tf32(w1.x); Ws[nbuf][lc + 9][lr] = to_tf32(w1.y);
            Ws[nbuf][lc +10][lr] = to_tf32(w1.z); Ws[nbuf][lc +11][lr] = to_tf32(w1.w);
            __syncthreads();
        }
    }

#pragma unroll
    for (int i = 0; i < 2; i++) {
#pragma unroll
        for (int j = 0; j < 8; j++) {
            int col = n0 + wn + j * 8 + 2 * tig;
            float b0 = bias ? bias[col] : 0.f;
            float b1 = bias ? bias[col + 1] : 0.f;
            int r0 = m0 + wm + i * 16 + gid;
            float2 v0 = make_float2(acc[i][j][0] + b0, acc[i][j][1] + b1);
            float2 v1 = make_float2(acc[i][j][2] + b0, acc[i][j][3] + b1);
            *(float2*)(C + (size_t)r0 * Ntot + col) = v0;
            *(float2*)(C + (size_t)(r0 + 8) * Ntot + col) = v1;
        }
    }
}

// ============ shared helpers for recurrent kernels ============
// dynamic smem layout (floats): ws[512*WS_STRIDE] | hs[2][64][68] | accs[64][52]
#define HS_OFF   (512 * WS_STRIDE)
#define ACC_OFF  (HS_OFF + 2 * 64 * 68)
#define REC_SMEM ((ACC_OFF + 64 * 52) * 4)

// stage one 64-k chunk of src rows [m0..m0+64) into hs buffer (tf32), regs pre-loaded
struct Stage { float4 v[4]; };

__device__ __forceinline__ void stage_load(Stage& s, const float* src, int m0, int m_l, int kq, int k0)
{
    const float4* p = (const float4*)(src + (size_t)(m0 + m_l) * D + k0 + kq);
    s.v[0] = __ldcg(p); s.v[1] = __ldcg(p + 1); s.v[2] = __ldcg(p + 2); s.v[3] = __ldcg(p + 3);
}

__device__ __forceinline__ void stage_store(float* hb, const Stage& s, int m_l, int kq)
{
    const float* f = (const float*)&s.v[0];
#pragma unroll
    for (int j = 0; j < 16; j++)
        hb[(kq + j) * 68 + m_l] = to_tf32(f[j]);
}

// run the K=512 mma loop: per warp one m16 tile (wm), NT n8 tiles at cols colb[t]
template<int NT>
__device__ __forceinline__ void rec_mma(const float* smem, const float* src, int m0,
                                        int m_l, int kq, int gid, int tig, int wm,
                                        const int* colb, float acc[][4])
{
    const float* ws = smem;
    float* hs = (float*)(smem + HS_OFF);
    Stage st;
    stage_load(st, src, m0, m_l, kq, 0);
    stage_store(hs, st, m_l, kq);
    __syncthreads();
    for (int c = 0; c < 8; c++) {
        if (c < 7) stage_load(st, src, m0, m_l, kq, (c + 1) * 64);
        const unsigned* hb = (const unsigned*)(hs + (c & 1) * 64 * 68);
        const unsigned* wu = (const unsigned*)ws;
        const int k0 = c * 64;
#pragma unroll
        for (int kk8 = 0; kk8 < 8; kk8++) {
            int kl = kk8 * 8;
            unsigned a0 = hb[(kl + tig) * 68 + wm + gid];
            unsigned a1 = hb[(kl + tig) * 68 + wm + gid + 8];
            unsigned a2 = hb[(kl + tig + 4) * 68 + wm + gid];
            unsigned a3 = hb[(kl + tig + 4) * 68 + wm + gid + 8];
#pragma unroll
            for (int t = 0; t < NT; t++) {
                unsigned b0 = wu[(k0 + kl + tig) * WS_STRIDE + colb[t] + gid];
                unsigned b1 = wu[(k0 + kl + tig + 4) * WS_STRIDE + colb[t] + gid];
                mma8(acc[t], a0, a1, a2, a3, b0, b1);
            }
        }
        __syncthreads();
        if (c < 7) {
            stage_store(hs + ((c & 1) ^ 1) * 64 * 68, st, m_l, kq);
            __syncthreads();
        }
    }
}

// scatter NT fragment tiles into accs[64][52] at cols fcol[t]
template<int NT>
__device__ __forceinline__ void frag_to_accs(float* smem, int wm, int gid, int tig,
                                             const int* fcol, float acc[][4])
{
    float* accs = smem + ACC_OFF;
#pragma unroll
    for (int t = 0; t < NT; t++) {
        int col = fcol[t] + 2 * tig;
        *(float2*)&accs[(wm + gid) * 52 + col]     = make_float2(acc[t][0], acc[t][1]);
        *(float2*)&accs[(wm + gid + 8) * 52 + col] = make_float2(acc[t][2], acc[t][3]);
    }
    __syncthreads();
}

// ---------------- GRU persistent kernel ----------------
// 128 CTAs = 4 m-groups(64) x 32 d-tiles(16). N = 48 (3 gates x 16 d).
__global__ void __launch_bounds__(THR, 1) gru_kernel(const float* __restrict__ whh,
                                                     const float* __restrict__ bhh)
{
    extern __shared__ float smem[];
    float* ws = smem;
    float* accs = smem + ACC_OFF;

    const int bid = blockIdx.x;
    const int mb = bid >> 5;
    const int m0 = mb * 64;
    const int fbase = mb * 32;
    const int d0 = (bid & 31) * 16;
    const int tid = threadIdx.x;
    const int wid = tid >> 5;
    const int lane = tid & 31;
    const int gid = lane >> 2;
    const int tig = lane & 3;
    const int wm = (wid >> 1) * 16;
    const int nh = wid & 1;
    const int mt = tid >> 4;
    const int dt = tid & 15;
    const int m_l = tid >> 2;
    const int kq = (tid & 3) * 16;
    const int d = d0 + dt;

    int colb[3] = { nh * 24, nh * 24 + 8, nh * 24 + 16 };

    for (int idx = tid; idx < 3 * 512 * 16; idx += THR) {
        int g = idx >> 13;
        int rem = idx & 8191;
        int k = rem >> 4;
        int dd = rem & 15;
        ws[k * WS_STRIDE + g * 16 + dd] = to_tf32(__ldg(whh + (size_t)(g * 512 + d0 + dd) * D + k));
    }
    for (int i = tid; i < 1024; i += THR)
        g_hA[bid * 1024 + i] = 0.f;

    const float bR = bhh[d], bZ = bhh[512 + d], bN = bhh[1024 + d];

    group_arrive(g_flagG, bid, 1);

    for (int l = 0; l < L; l++) {
        const float* __restrict__ hin = (l & 1) ? g_hB : g_hA;
        float* __restrict__ hout = (l & 1) ? g_hA : g_hB;
        group_wait(g_flagG, fbase, l + 1);

        float xr[4], xz[4], xn[4], hp[4];
#pragma unroll
        for (int i = 0; i < 4; i++) {
            int m = m0 + mt * 4 + i;
            size_t xb = ((size_t)m * L + l) * (size_t)K3 + d;
            xr[i] = __ldcg(&g_xproj[xb]);
            xz[i] = __ldcg(&g_xproj[xb + 512]);
            xn[i] = __ldcg(&g_xproj[xb + 1024]);
            hp[i] = __ldcg(hin + (size_t)m * D + d);
        }

        float acc[3][4];
#pragma unroll
        for (int t = 0; t < 3; t++)
#pragma unroll
            for (int q = 0; q < 4; q++) acc[t][q] = 0.f;

        rec_mma<3>(smem, hin, m0, m_l, kq, gid, tig, wm, colb, acc);
        frag_to_accs<3>(smem, wm, gid, tig, colb, acc);

#pragma unroll
        for (int i = 0; i < 4; i++) {
            int m = m0 + mt * 4 + i;
            int ml = mt * 4 + i;
            float r = sigmoidf_(xr[i] + accs[ml * 52 + dt] + bR);
            float z = sigmoidf_(xz[i] + accs[ml * 52 + 16 + dt] + bZ);
            float n = tanhf(xn[i] + r * (accs[ml * 52 + 32 + dt] + bN));
            float hnew = (1.f - z) * n + z * hp[i];
            __stcg(hout + (size_t)m * D + d, hnew);
            __stcg(&g_sstate[((size_t)m * L + l) * (size_t)D + d], hnew);
        }
        group_arrive(g_flagG, bid, l + 2);
    }
}

// ---------------- attention: logits + softmax over L ----------------
__global__ void attn_kernel()
{
    int b = blockIdx.x, tid = threadIdx.x;
    __shared__ float us[D];
    __shared__ float logits[L];
    __shared__ float red[8];
    for (int i = tid; i < D; i += 256) us[i] = g_uvec[b * D + i];
    __syncthreads();
    int wid = tid >> 5, lane = tid & 31;
    for (int l = wid; l < L; l += 8) {
        const float* sp = g_sstate + ((size_t)b * L + l) * D;
        float s = 0.f;
#pragma unroll
        for (int q = 0; q < 16; q++) s += sp[lane + 32 * q] * us[lane + 32 * q];
#pragma unroll
        for (int o = 16; o > 0; o >>= 1) s += __shfl_down_sync(0xffffffffu, s, o);
        if (lane == 0) logits[l] = s;
    }
    __syncthreads();
    float m = -1e30f;
    for (int i = tid; i < L; i += 256) m = fmaxf(m, logits[i]);
#pragma unroll
    for (int o = 16; o > 0; o >>= 1) m = fmaxf(m, __shfl_xor_sync(0xffffffffu, m, o));
    if (lane == 0) red[wid] = m;
    __syncthreads();
    m = red[0];
#pragma unroll
    for (int i = 1; i < 8; i++) m = fmaxf(m, red[i]);
    __syncthreads();
    float s = 0.f;
    for (int i = tid; i < L; i += 256) { float e = expf(logits[i] - m); logits[i] = e; s += e; }
#pragma unroll
    for (int o = 16; o > 0; o >>= 1) s += __shfl_xor_sync(0xffffffffu, s, o);
    if (lane == 0) red[wid] = s;
    __syncthreads();
    s = 0.f;
#pragma unroll
    for (int i = 0; i < 8; i++) s += red[i];
    float inv = 1.f / s;
    for (int i = tid; i < L; i += 256) g_att[b * L + i] = logits[i] * inv;
}

// ---------------- AUGRU persistent kernel ----------------
__global__ void __launch_bounds__(THR, 1) augru_kernel(const float* __restrict__ reset_w,
                                                       const float* __restrict__ update_w,
                                                       const float* __restrict__ hhat_w)
{
    extern __shared__ float smem[];
    float* ws = smem;
    float* accs = smem + ACC_OFF;

    const int bid = blockIdx.x;
    const int mb = bid >> 5;
    const int m0 = mb * 64;
    const int fbase = mb * 32;
    const int d0 = (bid & 31) * 16;
    const int tid = threadIdx.x;
    const int wid = tid >> 5;
    const int lane = tid & 31;
    const int gid = lane >> 2;
    const int tig = lane & 3;
    const int wm1 = (wid >> 1) * 16;      // phase1 m-tile
    const int nh1 = wid & 1;
    const int wm2 = (wid & 3) * 16;       // phase2 m-tile
    const int nh2 = wid >> 2;
    const int mt = tid >> 4;
    const int dt = tid & 15;
    const int m_l = tid >> 2;
    const int kq = (tid & 3) * 16;
    const int d = d0 + dt;

    int colb1[2] = { nh1 * 16, nh1 * 16 + 8 };   // reset (0..15) + update (16..31)
    int colb2[1] = { 32 + nh2 * 8 };             // hhat (32..47)
    int fcol2[1] = { nh2 * 8 };                  // scatter hhat accs to cols 0..15

    for (int idx = tid; idx < 3 * 512 * 16; idx += THR) {
        int g = idx >> 13;
        int rem = idx & 8191;
        int k = rem >> 4;
        int dd = rem & 15;
        const float* src = (g == 0) ? reset_w : (g == 1) ? update_w : hhat_w;
        ws[k * WS_STRIDE + g * 16 + dd] = to_tf32(__ldg(src + (size_t)(d0 + dd) * (2 * D) + k));
    }

    float hval[4], uu[4];
#pragma unroll
    for (int i = 0; i < 4; i++) {
        int m = m0 + mt * 4 + i;
        hval[i] = __ldcg(g_hA + (size_t)m * D + d);
        __stcg(&g_hB[(size_t)m * D + d], hval[i]);
    }
    group_arrive(g_flagA, bid, 1);

    for (int l = 0; l < L; l++) {
        // ---- phase 1: r, u gates (GEMM over h) ----
        group_wait(g_flagA, fbase, 2 * l + 1);

        float ar[4], au[4], at[4];
#pragma unroll
        for (int i = 0; i < 4; i++) {
            int m = m0 + mt * 4 + i;
            size_t ap = ((size_t)m * L + l) * (size_t)D + d;
            ar[i] = __ldcg(&g_apre0[ap]);
            au[i] = __ldcg(&g_apre1[ap]);
            at[i] = __ldcg(&g_att[m * L + l]);
        }

        float acc1[2][4];
#pragma unroll
        for (int t = 0; t < 2; t++)
#pragma unroll
            for (int q = 0; q < 4; q++) acc1[t][q] = 0.f;

        rec_mma<2>(smem, g_hB, m0, m_l, kq, gid, tig, wm1, colb1, acc1);
        frag_to_accs<2>(smem, wm1, gid, tig, colb1, acc1);

#pragma unroll
        for (int i = 0; i < 4; i++) {
            int m = m0 + mt * 4 + i;
            int ml = mt * 4 + i;
            float r = sigmoidf_(ar[i] + accs[ml * 52 + dt]);
            float u = sigmoidf_(au[i] + accs[ml * 52 + 16 + dt]);
            uu[i] = at[i] * u;
            __stcg(&g_rh[(size_t)m * D + d], r * hval[i]);
        }
        group_arrive(g_flagA, bid, 2 * l + 2);

        // ---- phase 2: h_hat (GEMM over r*h), update h ----
        group_wait(g_flagA, fbase, 2 * l + 2);

        float ah[4];
#pragma unroll
        for (int i = 0; i < 4; i++) {
            int m = m0 + mt * 4 + i;
            ah[i] = __ldcg(&g_apre2[((size_t)m * L + l) * (size_t)D + d]);
        }

        float acc2[1][4];
#pragma unroll
        for (int q = 0; q < 4; q++) acc2[0][q] = 0.f;

        rec_mma<1>(smem, g_rh, m0, m_l, kq, gid, tig, wm2, colb2, acc2);
        frag_to_accs<1>(smem, wm2, gid, tig, fcol2, acc2);

#pragma unroll
        for (int i = 0; i < 4; i++) {
            int m = m0 + mt * 4 + i;
            int ml = mt * 4 + i;
            float hh = tanhf(ah[i] + accs[ml * 52 + dt]);
            hval[i] = (1.f - uu[i]) * hval[i] + uu[i] * hh;
            __stcg(&g_hB[(size_t)m * D + d], hval[i]);
        }
        group_arrive(g_flagA, bid, 2 * l + 3);
    }
}

__global__ void copy_out_kernel(float* __restrict__ out)
{
    int i = blockIdx.x * 512 + threadIdx.x;
    out[i] = g_hB[i];
}

// ---------------- launch ----------------
extern "C" void kernel_launch(void* const* d_in, const int* in_sizes, int n_in,
                              void* d_out, int out_size)
{
    const float* session  = (const float*)d_in[0];
    const float* target   = (const float*)d_in[1];
    const float* w        = (const float*)d_in[2];
    const float* gru_wih  = (const float*)d_in[3];
    const float* gru_whh  = (const float*)d_in[4];
    const float* gru_bih  = (const float*)d_in[5];
    const float* gru_bhh  = (const float*)d_in[6];
    const float* reset_w  = (const float*)d_in[7];
    const float* reset_b  = (const float*)d_in[8];
    const float* update_w = (const float*)d_in[9];
    const float* update_b = (const float*)d_in[10];
    const float* hhat_w   = (const float*)d_in[11];
    const float* hhat_b   = (const float*)d_in[12];
    float* out = (float*)d_out;

    cudaFuncSetAttribute(gru_kernel,   cudaFuncAttributeMaxDynamicSharedMemorySize, REC_SMEM);
    cudaFuncSetAttribute(augru_kernel, cudaFuncAttributeMaxDynamicSharedMemorySize, REC_SMEM);

    reset_flags_kernel<<<1, 256>>>();
    // 1) x_proj = session @ wih^T + bih   [51200, 1536]
    gemm_tile128<<<dim3(12, 400), 256>>>(session, 0, gru_wih, 512, gru_bih, 0, K3);
    // 2) u = target @ w^T                 [256, 512]
    gemm_tile128<<<dim3(4, 2), 256>>>(target, 0, w, 512, (const float*)nullptr, 1, D);
    // 3) GRU recurrence
    gru_kernel<<<NB, THR, REC_SMEM>>>(gru_whh, gru_bhh);
    // 4) AUGRU x-side pre-projections: s_state @ W[:, D:2D]^T + b
    gemm_tile128<<<dim3(4, 400), 256>>>(session, 1, reset_w  + D, 2 * D, reset_b,  2, D);
    gemm_tile128<<<dim3(4, 400), 256>>>(session, 1, update_w + D, 2 * D, update_b, 3, D);
    gemm_tile128<<<dim3(4, 400), 256>>>(session, 1, hhat_w   + D, 2 * D, hhat_b,   4, D);
    // 5) attention softmax
    attn_kernel<<<B, 256>>>();
    // 6) AUGRU recurrence
    augru_kernel<<<NB, THR, REC_SMEM>>>(reset_w, update_w, hhat_w);
    // 7) output
    copy_out_kernel<<<B, 512>>>(out);
}